// round 1
// baseline (speedup 1.0000x reference)
#include <cuda_runtime.h>
#include <math.h>

#define NN    50000
#define EIN   800000
#define ETOT  850000
#define GMAX  64

// ---------------- scratch (device globals; no allocation allowed) ----------
__device__ int   g_deg[NN];
__device__ int   g_off[NN + 1];
__device__ int   g_fill[NN];
__device__ int   g_src[ETOT];
__device__ float g_es[NN * 8];
__device__ float g_ed[NN * 8];
__device__ float g_alpha[ETOT * 8];
__device__ float g_bufA[NN * 512];   // GEMM output h (per layer)
__device__ float g_bufB[NN * 512];   // aggregation output (next layer input)
__device__ float g_pool[GMAX * 512];
__device__ float g_cnt[GMAX];
__device__ float g_mlp[GMAX * 32];

// ---------------- CSR build ------------------------------------------------
__global__ void k_init() {
    int i = blockIdx.x * blockDim.x + threadIdx.x;
    if (i < NN) { g_deg[i] = 0; g_fill[i] = 0; }
}

__global__ void k_count(const int* __restrict__ ei) {
    int e = blockIdx.x * blockDim.x + threadIdx.x;
    if (e >= ETOT) return;
    int dst = (e < EIN) ? ei[EIN + e] : (e - EIN);
    atomicAdd(&g_deg[dst], 1);
}

__global__ void k_scan() {
    __shared__ int wsum[32];
    __shared__ int s_carry;
    int tid = threadIdx.x;
    if (tid == 0) s_carry = 0;
    __syncthreads();
    const int n = NN;
    int ntiles = (n + 1023) / 1024;
    for (int t = 0; t < ntiles; t++) {
        int idx = t * 1024 + tid;
        int v = (idx < n) ? g_deg[idx] : 0;
        int x = v;
        #pragma unroll
        for (int off = 1; off < 32; off <<= 1) {
            int y = __shfl_up_sync(0xffffffffu, x, off);
            if ((tid & 31) >= off) x += y;
        }
        if ((tid & 31) == 31) wsum[tid >> 5] = x;
        __syncthreads();
        if (tid < 32) {
            int w = wsum[tid];
            #pragma unroll
            for (int off = 1; off < 32; off <<= 1) {
                int y = __shfl_up_sync(0xffffffffu, w, off);
                if (tid >= off) w += y;
            }
            wsum[tid] = w;
        }
        __syncthreads();
        int incl = x + ((tid >= 32) ? wsum[(tid >> 5) - 1] : 0);
        int c = s_carry;
        if (idx < n) g_off[idx] = c + incl - v;
        __syncthreads();
        if (tid == 1023) s_carry = c + incl;
        __syncthreads();
    }
    if (tid == 0) g_off[n] = s_carry;
}

__global__ void k_fill(const int* __restrict__ ei) {
    int e = blockIdx.x * blockDim.x + threadIdx.x;
    if (e >= ETOT) return;
    int src, dst;
    if (e < EIN) { src = ei[e]; dst = ei[EIN + e]; }
    else         { src = e - EIN; dst = e - EIN; }
    int pos = g_off[dst] + atomicAdd(&g_fill[dst], 1);
    g_src[pos] = src;
}

// ---------------- fp32 GEMM: C[M,N] = A[M,K] * B[N,K]^T --------------------
// BM=BN=128, BK=8, 256 threads, 8x8 microtile.
__global__ __launch_bounds__(256)
void k_gemm(const float* __restrict__ Ain, const float* __restrict__ B,
            int M, int N, int K) {
    const float* A = Ain ? Ain : g_bufB;
    float* C = g_bufA;
    __shared__ float As[8][128];
    __shared__ float Bs[8][128];
    int tid = threadIdx.x;
    int bm = blockIdx.y, bn = blockIdx.x;
    int arow = tid >> 1;
    int ak = (tid & 1) * 4;
    int grow = bm * 128 + arow;
    int gcol = bn * 128 + arow;
    const float* Aptr = A + (size_t)grow * K + ak;
    const float* Bptr = B + (size_t)gcol * K + ak;
    float acc[8][8];
    #pragma unroll
    for (int i = 0; i < 8; i++)
        #pragma unroll
        for (int j = 0; j < 8; j++) acc[i][j] = 0.f;

    int ty = tid >> 4, tx = tid & 15;
    for (int k0 = 0; k0 < K; k0 += 8) {
        float4 av = (grow < M) ? *(const float4*)(Aptr + k0) : make_float4(0, 0, 0, 0);
        float4 bv = *(const float4*)(Bptr + k0);
        As[ak + 0][arow] = av.x; As[ak + 1][arow] = av.y;
        As[ak + 2][arow] = av.z; As[ak + 3][arow] = av.w;
        Bs[ak + 0][arow] = bv.x; Bs[ak + 1][arow] = bv.y;
        Bs[ak + 2][arow] = bv.z; Bs[ak + 3][arow] = bv.w;
        __syncthreads();
        #pragma unroll
        for (int k = 0; k < 8; k++) {
            float a[8], b[8];
            float4 a0 = *(const float4*)&As[k][ty * 8];
            float4 a1 = *(const float4*)&As[k][ty * 8 + 4];
            float4 b0 = *(const float4*)&Bs[k][tx * 8];
            float4 b1 = *(const float4*)&Bs[k][tx * 8 + 4];
            a[0]=a0.x;a[1]=a0.y;a[2]=a0.z;a[3]=a0.w;a[4]=a1.x;a[5]=a1.y;a[6]=a1.z;a[7]=a1.w;
            b[0]=b0.x;b[1]=b0.y;b[2]=b0.z;b[3]=b0.w;b[4]=b1.x;b[5]=b1.y;b[6]=b1.z;b[7]=b1.w;
            #pragma unroll
            for (int i = 0; i < 8; i++)
                #pragma unroll
                for (int j = 0; j < 8; j++)
                    acc[i][j] = fmaf(a[i], b[j], acc[i][j]);
        }
        __syncthreads();
    }
    #pragma unroll
    for (int i = 0; i < 8; i++) {
        int m = bm * 128 + ty * 8 + i;
        if (m < M) {
            float* cp = C + (size_t)m * N + bn * 128 + tx * 8;
            *(float4*)cp       = make_float4(acc[i][0], acc[i][1], acc[i][2], acc[i][3]);
            *(float4*)(cp + 4) = make_float4(acc[i][4], acc[i][5], acc[i][6], acc[i][7]);
        }
    }
}

// ---------------- attention coefficients es/ed ------------------------------
__global__ void k_attn(const float* __restrict__ as_, const float* __restrict__ ad_,
                       int Fout, int C) {
    int t = blockIdx.x * blockDim.x + threadIdx.x;
    if (t >= NN * 8) return;
    int n = t >> 3, hd = t & 7;
    const float* hp = g_bufA + (size_t)n * Fout + hd * C;
    const float* ap = as_ + hd * C;
    const float* dp = ad_ + hd * C;
    float s = 0.f, d = 0.f;
    for (int c = 0; c < C; c++) {
        float v = __ldg(hp + c);
        s += v * __ldg(ap + c);
        d += v * __ldg(dp + c);
    }
    g_es[t] = s;
    g_ed[t] = d;
}

// ---------------- edge softmax (warp per dst node) --------------------------
__global__ void k_softmax() {
    int w = (blockIdx.x * blockDim.x + threadIdx.x) >> 5;
    if (w >= NN) return;
    int lane = threadIdx.x & 31;
    int head = lane & 7, sub = lane >> 3;
    int beg = g_off[w];
    int deg = g_off[w + 1] - beg;
    float edv = g_ed[w * 8 + head];
    float mx = -3.0e38f;
    for (int i = sub; i < deg; i += 4) {
        int s = g_src[beg + i];
        float e = g_es[s * 8 + head] + edv;
        e = e > 0.f ? e : 0.2f * e;
        g_alpha[(beg + i) * 8 + head] = e;
        mx = fmaxf(mx, e);
    }
    mx = fmaxf(mx, __shfl_xor_sync(0xffffffffu, mx, 8));
    mx = fmaxf(mx, __shfl_xor_sync(0xffffffffu, mx, 16));
    float sm = 0.f;
    for (int i = sub; i < deg; i += 4) {
        float ex = __expf(g_alpha[(beg + i) * 8 + head] - mx);
        g_alpha[(beg + i) * 8 + head] = ex;
        sm += ex;
    }
    sm += __shfl_xor_sync(0xffffffffu, sm, 8);
    sm += __shfl_xor_sync(0xffffffffu, sm, 16);
    float inv = 1.f / sm;
    for (int i = sub; i < deg; i += 4)
        g_alpha[(beg + i) * 8 + head] *= inv;
}

// ---------------- aggregation (warp per dst node) ---------------------------
template <int REGS, int LOG2C, bool ELU>
__global__ void k_agg(const float* __restrict__ bias) {
    int w = (blockIdx.x * blockDim.x + threadIdx.x) >> 5;
    if (w >= NN) return;
    int lane = threadIdx.x & 31;
    int beg = g_off[w], end = g_off[w + 1];
    const int Fout = REGS * 32;
    float acc[REGS];
    #pragma unroll
    for (int r = 0; r < REGS; r++) acc[r] = 0.f;
    for (int i = beg; i < end; i++) {
        int s = g_src[i];
        float a8 = (lane < 8) ? g_alpha[i * 8 + lane] : 0.f;
        const float* hp = g_bufA + (size_t)s * Fout;
        #pragma unroll
        for (int r = 0; r < REGS; r++) {
            int f = r * 32 + lane;
            float al = __shfl_sync(0xffffffffu, a8, f >> LOG2C);
            acc[r] = fmaf(al, __ldg(hp + f), acc[r]);
        }
    }
    float* op = g_bufB + (size_t)w * Fout;
    #pragma unroll
    for (int r = 0; r < REGS; r++) {
        int f = r * 32 + lane;
        float v = acc[r] + __ldg(bias + f);
        if (ELU) v = v > 0.f ? v : expm1f(v);
        op[f] = v;
    }
}

// ---------------- pooling ----------------------------------------------------
__global__ void k_pool_init() {
    int i = blockIdx.x * blockDim.x + threadIdx.x;
    if (i < GMAX * 512) g_pool[i] = 0.f;
    if (i < GMAX) g_cnt[i] = 0.f;
}

__global__ void k_pool(const int* __restrict__ batch) {
    int f = threadIdx.x;            // 512 threads = features
    int n0 = blockIdx.x * 512;
    int n1 = n0 + 512; if (n1 > NN) n1 = NN;
    if (n0 >= NN) return;
    float acc = 0.f;
    int cur = __ldg(&batch[n0]);
    for (int n = n0; n < n1; n++) {
        int b = __ldg(&batch[n]);
        if (b != cur) { atomicAdd(&g_pool[cur * 512 + f], acc); acc = 0.f; cur = b; }
        acc += g_bufB[(size_t)n * 512 + f];
    }
    atomicAdd(&g_pool[cur * 512 + f], acc);
}

__global__ void k_cnt(const int* __restrict__ batch) {
    int n = blockIdx.x * blockDim.x + threadIdx.x;
    if (n < NN) atomicAdd(&g_cnt[batch[n]], 1.f);
}

// ---------------- MLP head ---------------------------------------------------
__global__ void k_mlp1(const float* __restrict__ lw1, const float* __restrict__ lb1) {
    int t = blockIdx.x * blockDim.x + threadIdx.x;
    if (t >= GMAX * 32) return;
    int g = t >> 5, j = t & 31;
    float inv = 1.f / fmaxf(g_cnt[g], 1.f);
    const float* pp = g_pool + g * 512;
    const float* wp = lw1 + j * 512;
    float s = 0.f;
    for (int k = 0; k < 512; k++) s += pp[k] * __ldg(wp + k);
    s = s * inv + __ldg(lb1 + j);
    g_mlp[t] = s > 0.f ? s : expm1f(s);
}

__global__ void k_mlp2(const float* __restrict__ lw2, const float* __restrict__ lb2,
                       float* __restrict__ out) {
    int t = threadIdx.x;
    if (t >= GMAX * 2) return;
    int g = t >> 1, o = t & 1;
    const float* mp = g_mlp + g * 32;
    const float* wp = lw2 + o * 32;
    float s = 0.f;
    #pragma unroll
    for (int k = 0; k < 32; k++) s += mp[k] * __ldg(wp + k);
    out[t] = s + __ldg(lb2 + o);
}

// ---------------- launch -----------------------------------------------------
extern "C" void kernel_launch(void* const* d_in, const int* in_sizes, int n_in,
                              void* d_out, int out_size) {
    const float* x     = (const float*)d_in[0];
    const int*   ei    = (const int*)  d_in[1];
    const int*   batch = (const int*)  d_in[2];
    const float *W[4], *as_[4], *ad_[4], *bb[4];
    for (int l = 0; l < 4; l++) {
        W[l]   = (const float*)d_in[3 + l * 4];
        as_[l] = (const float*)d_in[4 + l * 4];
        ad_[l] = (const float*)d_in[5 + l * 4];
        bb[l]  = (const float*)d_in[6 + l * 4];
    }
    const float* lw1 = (const float*)d_in[19];
    const float* lb1 = (const float*)d_in[20];
    const float* lw2 = (const float*)d_in[21];
    const float* lb2 = (const float*)d_in[22];
    float* out = (float*)d_out;

    // CSR build (by dst, with self loops appended)
    k_init <<<(NN + 255) / 256, 256>>>();
    k_count<<<(ETOT + 255) / 256, 256>>>(ei);
    k_scan <<<1, 1024>>>();
    k_fill <<<(ETOT + 255) / 256, 256>>>(ei);

    const int Fin[4] = {128, 512, 256, 128};
    const int Fo[4]  = {512, 256, 128, 512};
    const int Cc[4]  = {64, 32, 16, 64};

    for (int l = 0; l < 4; l++) {
        const float* in = (l == 0) ? x : nullptr;  // nullptr => g_bufB
        dim3 gg(Fo[l] / 128, (NN + 127) / 128);
        k_gemm<<<gg, 256>>>(in, W[l], NN, Fo[l], Fin[l]);
        k_attn<<<(NN * 8 + 255) / 256, 256>>>(as_[l], ad_[l], Fo[l], Cc[l]);
        k_softmax<<<(NN + 7) / 8, 256>>>();
        int blocks = (NN * 32 + 255) / 256;
        if      (l == 0) k_agg<16, 6, true ><<<blocks, 256>>>(bb[l]);
        else if (l == 1) k_agg< 8, 5, true ><<<blocks, 256>>>(bb[l]);
        else if (l == 2) k_agg< 4, 4, true ><<<blocks, 256>>>(bb[l]);
        else             k_agg<16, 6, false><<<blocks, 256>>>(bb[l]);
    }

    k_pool_init<<<(GMAX * 512 + 255) / 256, 256>>>();
    k_pool<<<(NN + 511) / 512, 512>>>(batch);
    k_cnt <<<(NN + 255) / 256, 256>>>(batch);
    k_mlp1<<<8, 256>>>(lw1, lb1);
    k_mlp2<<<1, 128>>>(lw2, lb2, out);
}

// round 2
// speedup vs baseline: 1.2242x; 1.2242x over previous
#include <cuda_runtime.h>
#include <math.h>
#include <stdint.h>

#define NN    50000
#define EIN   800000
#define ETOT  850000
#define GMAX  64

// ---------------- scratch (device globals; no allocation allowed) ----------
__device__ int   g_deg[NN];
__device__ int   g_off[NN + 1];
__device__ int   g_fill[NN];
__device__ int   g_src[ETOT];
__device__ float g_es[NN * 8];
__device__ float g_ed[NN * 8];
__device__ float g_alpha[ETOT * 8];
__device__ float g_bufA[NN * 512];   // GEMM output h (per layer)
__device__ float g_bufB[NN * 512];   // aggregation output (next layer input)
__device__ float g_pool[GMAX * 512];
__device__ float g_cnt[GMAX];
__device__ float g_mlp[GMAX * 32];

// ---------------- CSR build ------------------------------------------------
__global__ void k_init() {
    int i = blockIdx.x * blockDim.x + threadIdx.x;
    if (i < NN) { g_deg[i] = 0; g_fill[i] = 0; }
}

__global__ void k_count(const int* __restrict__ ei) {
    int e = blockIdx.x * blockDim.x + threadIdx.x;
    if (e >= ETOT) return;
    int dst = (e < EIN) ? ei[EIN + e] : (e - EIN);
    atomicAdd(&g_deg[dst], 1);
}

__global__ void k_scan() {
    __shared__ int wsum[32];
    __shared__ int s_carry;
    int tid = threadIdx.x;
    if (tid == 0) s_carry = 0;
    __syncthreads();
    const int n = NN;
    int ntiles = (n + 1023) / 1024;
    for (int t = 0; t < ntiles; t++) {
        int idx = t * 1024 + tid;
        int v = (idx < n) ? g_deg[idx] : 0;
        int x = v;
        #pragma unroll
        for (int off = 1; off < 32; off <<= 1) {
            int y = __shfl_up_sync(0xffffffffu, x, off);
            if ((tid & 31) >= off) x += y;
        }
        if ((tid & 31) == 31) wsum[tid >> 5] = x;
        __syncthreads();
        if (tid < 32) {
            int w = wsum[tid];
            #pragma unroll
            for (int off = 1; off < 32; off <<= 1) {
                int y = __shfl_up_sync(0xffffffffu, w, off);
                if (tid >= off) w += y;
            }
            wsum[tid] = w;
        }
        __syncthreads();
        int incl = x + ((tid >= 32) ? wsum[(tid >> 5) - 1] : 0);
        int c = s_carry;
        if (idx < n) g_off[idx] = c + incl - v;
        __syncthreads();
        if (tid == 1023) s_carry = c + incl;
        __syncthreads();
    }
    if (tid == 0) g_off[n] = s_carry;
}

__global__ void k_fill(const int* __restrict__ ei) {
    int e = blockIdx.x * blockDim.x + threadIdx.x;
    if (e >= ETOT) return;
    int src, dst;
    if (e < EIN) { src = ei[e]; dst = ei[EIN + e]; }
    else         { src = e - EIN; dst = e - EIN; }
    int pos = g_off[dst] + atomicAdd(&g_fill[dst], 1);
    g_src[pos] = src;
}

// ---------------- tf32 tensor-core GEMM: C[M,N] = A[M,K] * B[N,K]^T ---------
// Block tile 128x128, BK=16, 256 threads (8 warps, each 64x32),
// mma.sync.m16n8k8 tf32, double-buffered smem with stride-20 padding
// (conflict-free fragment LDS).
#define SMS 20  // smem row stride in floats

__device__ __forceinline__ uint32_t f2tf32(float f) {
    uint32_t u;
    asm("cvt.rna.tf32.f32 %0, %1;" : "=r"(u) : "f"(f));
    return u;
}

__global__ __launch_bounds__(256, 1)
void k_gemm_tf32(const float* __restrict__ Ain, const float* __restrict__ B,
                 int M, int N, int K) {
    const float* A = Ain ? Ain : g_bufB;
    float* C = g_bufA;

    __shared__ float As[2][128 * SMS];
    __shared__ float Bs[2][128 * SMS];

    const int tid  = threadIdx.x;
    const int lane = tid & 31;
    const int wid  = tid >> 5;
    const int gid  = lane >> 2;     // 0..7
    const int tg   = lane & 3;      // 0..3
    const int wm   = (wid >> 2) * 64;  // 0 or 64
    const int wn   = (wid & 3) * 32;   // 0,32,64,96

    const int bm = blockIdx.y * 128;
    const int bn = blockIdx.x * 128;

    // global load assignment: 2 float4 each for A and B per chunk
    const int r0 = tid >> 2;              // rows 0..63
    const int kq = (tid & 3) * 4;         // k offset 0,4,8,12

    float acc[4][4][4];
    #pragma unroll
    for (int mt = 0; mt < 4; mt++)
        #pragma unroll
        for (int nt = 0; nt < 4; nt++)
            #pragma unroll
            for (int i = 0; i < 4; i++) acc[mt][nt][i] = 0.f;

    const int KC = K >> 4;

    float4 ra0, ra1, rb0, rb1;
    // prologue load chunk 0
    {
        int am0 = bm + r0, am1 = bm + r0 + 64;
        ra0 = (am0 < M) ? *(const float4*)(A + (size_t)am0 * K + kq) : make_float4(0,0,0,0);
        ra1 = (am1 < M) ? *(const float4*)(A + (size_t)am1 * K + kq) : make_float4(0,0,0,0);
        rb0 = *(const float4*)(B + (size_t)(bn + r0) * K + kq);
        rb1 = *(const float4*)(B + (size_t)(bn + r0 + 64) * K + kq);
    }
    // store chunk 0 into buffer 0 (tf32-rounded)
    {
        float* ap = &As[0][r0 * SMS + kq];
        float* bp = &Bs[0][r0 * SMS + kq];
        ap[0]=__uint_as_float(f2tf32(ra0.x)); ap[1]=__uint_as_float(f2tf32(ra0.y));
        ap[2]=__uint_as_float(f2tf32(ra0.z)); ap[3]=__uint_as_float(f2tf32(ra0.w));
        ap[64*SMS+0]=__uint_as_float(f2tf32(ra1.x)); ap[64*SMS+1]=__uint_as_float(f2tf32(ra1.y));
        ap[64*SMS+2]=__uint_as_float(f2tf32(ra1.z)); ap[64*SMS+3]=__uint_as_float(f2tf32(ra1.w));
        bp[0]=__uint_as_float(f2tf32(rb0.x)); bp[1]=__uint_as_float(f2tf32(rb0.y));
        bp[2]=__uint_as_float(f2tf32(rb0.z)); bp[3]=__uint_as_float(f2tf32(rb0.w));
        bp[64*SMS+0]=__uint_as_float(f2tf32(rb1.x)); bp[64*SMS+1]=__uint_as_float(f2tf32(rb1.y));
        bp[64*SMS+2]=__uint_as_float(f2tf32(rb1.z)); bp[64*SMS+3]=__uint_as_float(f2tf32(rb1.w));
    }
    __syncthreads();

    for (int kc = 0; kc < KC; kc++) {
        // prefetch next chunk from global
        if (kc + 1 < KC) {
            int koff = (kc + 1) * 16 + kq;
            int am0 = bm + r0, am1 = bm + r0 + 64;
            ra0 = (am0 < M) ? *(const float4*)(A + (size_t)am0 * K + koff) : make_float4(0,0,0,0);
            ra1 = (am1 < M) ? *(const float4*)(A + (size_t)am1 * K + koff) : make_float4(0,0,0,0);
            rb0 = *(const float4*)(B + (size_t)(bn + r0) * K + koff);
            rb1 = *(const float4*)(B + (size_t)(bn + r0 + 64) * K + koff);
        }

        // compute on buffer kc&1
        const float* as = As[kc & 1];
        const float* bs = Bs[kc & 1];
        #pragma unroll
        for (int s = 0; s < 2; s++) {
            int kl = s * 8;
            uint32_t af[4][4], bf[4][2];
            #pragma unroll
            for (int mt = 0; mt < 4; mt++) {
                int m = wm + mt * 16 + gid;
                af[mt][0] = __float_as_uint(as[m * SMS + kl + tg]);
                af[mt][1] = __float_as_uint(as[(m + 8) * SMS + kl + tg]);
                af[mt][2] = __float_as_uint(as[m * SMS + kl + tg + 4]);
                af[mt][3] = __float_as_uint(as[(m + 8) * SMS + kl + tg + 4]);
            }
            #pragma unroll
            for (int nt = 0; nt < 4; nt++) {
                int n = wn + nt * 8 + gid;
                bf[nt][0] = __float_as_uint(bs[n * SMS + kl + tg]);
                bf[nt][1] = __float_as_uint(bs[n * SMS + kl + tg + 4]);
            }
            #pragma unroll
            for (int mt = 0; mt < 4; mt++)
                #pragma unroll
                for (int nt = 0; nt < 4; nt++) {
                    asm volatile(
                        "mma.sync.aligned.m16n8k8.row.col.f32.tf32.tf32.f32 "
                        "{%0,%1,%2,%3}, {%4,%5,%6,%7}, {%8,%9}, {%0,%1,%2,%3};"
                        : "+f"(acc[mt][nt][0]), "+f"(acc[mt][nt][1]),
                          "+f"(acc[mt][nt][2]), "+f"(acc[mt][nt][3])
                        : "r"(af[mt][0]), "r"(af[mt][1]), "r"(af[mt][2]), "r"(af[mt][3]),
                          "r"(bf[nt][0]), "r"(bf[nt][1]));
                }
        }

        __syncthreads();
        if (kc + 1 < KC) {
            float* ap = &As[(kc + 1) & 1][r0 * SMS + kq];
            float* bp = &Bs[(kc + 1) & 1][r0 * SMS + kq];
            ap[0]=__uint_as_float(f2tf32(ra0.x)); ap[1]=__uint_as_float(f2tf32(ra0.y));
            ap[2]=__uint_as_float(f2tf32(ra0.z)); ap[3]=__uint_as_float(f2tf32(ra0.w));
            ap[64*SMS+0]=__uint_as_float(f2tf32(ra1.x)); ap[64*SMS+1]=__uint_as_float(f2tf32(ra1.y));
            ap[64*SMS+2]=__uint_as_float(f2tf32(ra1.z)); ap[64*SMS+3]=__uint_as_float(f2tf32(ra1.w));
            bp[0]=__uint_as_float(f2tf32(rb0.x)); bp[1]=__uint_as_float(f2tf32(rb0.y));
            bp[2]=__uint_as_float(f2tf32(rb0.z)); bp[3]=__uint_as_float(f2tf32(rb0.w));
            bp[64*SMS+0]=__uint_as_float(f2tf32(rb1.x)); bp[64*SMS+1]=__uint_as_float(f2tf32(rb1.y));
            bp[64*SMS+2]=__uint_as_float(f2tf32(rb1.z)); bp[64*SMS+3]=__uint_as_float(f2tf32(rb1.w));
            __syncthreads();
        }
    }

    // epilogue
    #pragma unroll
    for (int mt = 0; mt < 4; mt++) {
        int gm0 = bm + wm + mt * 16 + gid;
        int gm1 = gm0 + 8;
        #pragma unroll
        for (int nt = 0; nt < 4; nt++) {
            int gn = bn + wn + nt * 8 + tg * 2;
            if (gm0 < M)
                *(float2*)(C + (size_t)gm0 * N + gn) = make_float2(acc[mt][nt][0], acc[mt][nt][1]);
            if (gm1 < M)
                *(float2*)(C + (size_t)gm1 * N + gn) = make_float2(acc[mt][nt][2], acc[mt][nt][3]);
        }
    }
}

// ---------------- attention coefficients es/ed ------------------------------
__global__ void k_attn(const float* __restrict__ as_, const float* __restrict__ ad_,
                       int Fout, int C) {
    int t = blockIdx.x * blockDim.x + threadIdx.x;
    if (t >= NN * 8) return;
    int n = t >> 3, hd = t & 7;
    const float* hp = g_bufA + (size_t)n * Fout + hd * C;
    const float* ap = as_ + hd * C;
    const float* dp = ad_ + hd * C;
    float s = 0.f, d = 0.f;
    for (int c = 0; c < C; c++) {
        float v = __ldg(hp + c);
        s += v * __ldg(ap + c);
        d += v * __ldg(dp + c);
    }
    g_es[t] = s;
    g_ed[t] = d;
}

// ---------------- edge softmax (warp per dst node) --------------------------
__global__ void k_softmax() {
    int w = (blockIdx.x * blockDim.x + threadIdx.x) >> 5;
    if (w >= NN) return;
    int lane = threadIdx.x & 31;
    int head = lane & 7, sub = lane >> 3;
    int beg = g_off[w];
    int deg = g_off[w + 1] - beg;
    float edv = g_ed[w * 8 + head];
    float mx = -3.0e38f;
    for (int i = sub; i < deg; i += 4) {
        int s = g_src[beg + i];
        float e = g_es[s * 8 + head] + edv;
        e = e > 0.f ? e : 0.2f * e;
        g_alpha[(beg + i) * 8 + head] = e;
        mx = fmaxf(mx, e);
    }
    mx = fmaxf(mx, __shfl_xor_sync(0xffffffffu, mx, 8));
    mx = fmaxf(mx, __shfl_xor_sync(0xffffffffu, mx, 16));
    float sm = 0.f;
    for (int i = sub; i < deg; i += 4) {
        float ex = __expf(g_alpha[(beg + i) * 8 + head] - mx);
        g_alpha[(beg + i) * 8 + head] = ex;
        sm += ex;
    }
    sm += __shfl_xor_sync(0xffffffffu, sm, 8);
    sm += __shfl_xor_sync(0xffffffffu, sm, 16);
    float inv = 1.f / sm;
    for (int i = sub; i < deg; i += 4)
        g_alpha[(beg + i) * 8 + head] *= inv;
}

// ---------------- aggregation (warp per dst node) ---------------------------
template <int REGS, int LOG2C, bool ELU>
__global__ void k_agg(const float* __restrict__ bias) {
    int w = (blockIdx.x * blockDim.x + threadIdx.x) >> 5;
    if (w >= NN) return;
    int lane = threadIdx.x & 31;
    int beg = g_off[w], end = g_off[w + 1];
    const int Fout = REGS * 32;
    float acc[REGS];
    #pragma unroll
    for (int r = 0; r < REGS; r++) acc[r] = 0.f;
    for (int i = beg; i < end; i++) {
        int s = g_src[i];
        float a8 = (lane < 8) ? g_alpha[i * 8 + lane] : 0.f;
        const float* hp = g_bufA + (size_t)s * Fout;
        #pragma unroll
        for (int r = 0; r < REGS; r++) {
            int f = r * 32 + lane;
            float al = __shfl_sync(0xffffffffu, a8, f >> LOG2C);
            acc[r] = fmaf(al, __ldg(hp + f), acc[r]);
        }
    }
    float* op = g_bufB + (size_t)w * Fout;
    #pragma unroll
    for (int r = 0; r < REGS; r++) {
        int f = r * 32 + lane;
        float v = acc[r] + __ldg(bias + f);
        if (ELU) v = v > 0.f ? v : expm1f(v);
        op[f] = v;
    }
}

// ---------------- pooling ----------------------------------------------------
__global__ void k_pool_init() {
    int i = blockIdx.x * blockDim.x + threadIdx.x;
    if (i < GMAX * 512) g_pool[i] = 0.f;
    if (i < GMAX) g_cnt[i] = 0.f;
}

__global__ void k_pool(const int* __restrict__ batch) {
    int f = threadIdx.x;            // 512 threads = features
    int n0 = blockIdx.x * 512;
    int n1 = n0 + 512; if (n1 > NN) n1 = NN;
    if (n0 >= NN) return;
    float acc = 0.f;
    int cur = __ldg(&batch[n0]);
    for (int n = n0; n < n1; n++) {
        int b = __ldg(&batch[n]);
        if (b != cur) { atomicAdd(&g_pool[cur * 512 + f], acc); acc = 0.f; cur = b; }
        acc += g_bufB[(size_t)n * 512 + f];
    }
    atomicAdd(&g_pool[cur * 512 + f], acc);
}

__global__ void k_cnt(const int* __restrict__ batch) {
    int n = blockIdx.x * blockDim.x + threadIdx.x;
    if (n < NN) atomicAdd(&g_cnt[batch[n]], 1.f);
}

// ---------------- MLP head ---------------------------------------------------
__global__ void k_mlp1(const float* __restrict__ lw1, const float* __restrict__ lb1) {
    int t = blockIdx.x * blockDim.x + threadIdx.x;
    if (t >= GMAX * 32) return;
    int g = t >> 5, j = t & 31;
    float inv = 1.f / fmaxf(g_cnt[g], 1.f);
    const float* pp = g_pool + g * 512;
    const float* wp = lw1 + j * 512;
    float s = 0.f;
    for (int k = 0; k < 512; k++) s += pp[k] * __ldg(wp + k);
    s = s * inv + __ldg(lb1 + j);
    g_mlp[t] = s > 0.f ? s : expm1f(s);
}

__global__ void k_mlp2(const float* __restrict__ lw2, const float* __restrict__ lb2,
                       float* __restrict__ out) {
    int t = threadIdx.x;
    if (t >= GMAX * 2) return;
    int g = t >> 1, o = t & 1;
    const float* mp = g_mlp + g * 32;
    const float* wp = lw2 + o * 32;
    float s = 0.f;
    #pragma unroll
    for (int k = 0; k < 32; k++) s += mp[k] * __ldg(wp + k);
    out[t] = s + __ldg(lb2 + o);
}

// ---------------- launch -----------------------------------------------------
extern "C" void kernel_launch(void* const* d_in, const int* in_sizes, int n_in,
                              void* d_out, int out_size) {
    const float* x     = (const float*)d_in[0];
    const int*   ei    = (const int*)  d_in[1];
    const int*   batch = (const int*)  d_in[2];
    const float *W[4], *as_[4], *ad_[4], *bb[4];
    for (int l = 0; l < 4; l++) {
        W[l]   = (const float*)d_in[3 + l * 4];
        as_[l] = (const float*)d_in[4 + l * 4];
        ad_[l] = (const float*)d_in[5 + l * 4];
        bb[l]  = (const float*)d_in[6 + l * 4];
    }
    const float* lw1 = (const float*)d_in[19];
    const float* lb1 = (const float*)d_in[20];
    const float* lw2 = (const float*)d_in[21];
    const float* lb2 = (const float*)d_in[22];
    float* out = (float*)d_out;

    // CSR build (by dst, with self loops appended)
    k_init <<<(NN + 255) / 256, 256>>>();
    k_count<<<(ETOT + 255) / 256, 256>>>(ei);
    k_scan <<<1, 1024>>>();
    k_fill <<<(ETOT + 255) / 256, 256>>>(ei);

    const int Fin[4] = {128, 512, 256, 128};
    const int Fo[4]  = {512, 256, 128, 512};
    const int Cc[4]  = {64, 32, 16, 64};

    for (int l = 0; l < 4; l++) {
        const float* in = (l == 0) ? x : nullptr;  // nullptr => g_bufB
        dim3 gg(Fo[l] / 128, (NN + 127) / 128);
        k_gemm_tf32<<<gg, 256>>>(in, W[l], NN, Fo[l], Fin[l]);
        k_attn<<<(NN * 8 + 255) / 256, 256>>>(as_[l], ad_[l], Fo[l], Cc[l]);
        k_softmax<<<(NN + 7) / 8, 256>>>();
        int blocks = (NN * 32 + 255) / 256;
        if      (l == 0) k_agg<16, 6, true ><<<blocks, 256>>>(bb[l]);
        else if (l == 1) k_agg< 8, 5, true ><<<blocks, 256>>>(bb[l]);
        else if (l == 2) k_agg< 4, 4, true ><<<blocks, 256>>>(bb[l]);
        else             k_agg<16, 6, false><<<blocks, 256>>>(bb[l]);
    }

    k_pool_init<<<(GMAX * 512 + 255) / 256, 256>>>();
    k_pool<<<(NN + 511) / 512, 512>>>(batch);
    k_cnt <<<(NN + 255) / 256, 256>>>(batch);
    k_mlp1<<<8, 256>>>(lw1, lb1);
    k_mlp2<<<1, 128>>>(lw2, lb2, out);
}

// round 3
// speedup vs baseline: 1.4385x; 1.1750x over previous
#include <cuda_runtime.h>
#include <math.h>
#include <stdint.h>

#define NN    50000
#define EIN   800000
#define ETOT  850000
#define GMAX  64

// ---------------- scratch (device globals; zero-initialized at load) -------
__device__ int   g_deg[NN];
__device__ int   g_off[NN + 1];
__device__ int   g_fill[NN];
__device__ int   g_src[ETOT];
__device__ float g_es[NN * 8];
__device__ float g_ed[NN * 8];
__device__ float g_inv[NN * 8];
__device__ float g_alpha[ETOT * 8];
__device__ float g_bufA[NN * 512];   // GEMM output h (per layer)
__device__ float g_bufB[NN * 512];   // aggregation output (next layer input)
__device__ float g_pool[GMAX * 512];
__device__ float g_cnt[GMAX];
__device__ float g_mlp[GMAX * 32];

// ---------------- CSR build ------------------------------------------------
// NOTE: g_deg/g_fill are zero at first call (static zero-init) and re-zeroed
// by k_clear at the tail of every launch, so no front-side init is needed.
__global__ void k_count(const int* __restrict__ ei) {
    int e = blockIdx.x * blockDim.x + threadIdx.x;
    if (e >= ETOT) return;
    int dst = (e < EIN) ? ei[EIN + e] : (e - EIN);
    atomicAdd(&g_deg[dst], 1);
}

__global__ void k_scan() {
    __shared__ int wsum[32];
    __shared__ int s_carry;
    int tid = threadIdx.x;
    if (tid == 0) s_carry = 0;
    __syncthreads();
    const int n = NN;
    int ntiles = (n + 1023) / 1024;
    for (int t = 0; t < ntiles; t++) {
        int idx = t * 1024 + tid;
        int v = (idx < n) ? g_deg[idx] : 0;
        int x = v;
        #pragma unroll
        for (int off = 1; off < 32; off <<= 1) {
            int y = __shfl_up_sync(0xffffffffu, x, off);
            if ((tid & 31) >= off) x += y;
        }
        if ((tid & 31) == 31) wsum[tid >> 5] = x;
        __syncthreads();
        if (tid < 32) {
            int w = wsum[tid];
            #pragma unroll
            for (int off = 1; off < 32; off <<= 1) {
                int y = __shfl_up_sync(0xffffffffu, w, off);
                if (tid >= off) w += y;
            }
            wsum[tid] = w;
        }
        __syncthreads();
        int incl = x + ((tid >= 32) ? wsum[(tid >> 5) - 1] : 0);
        int c = s_carry;
        if (idx < n) g_off[idx] = c + incl - v;
        __syncthreads();
        if (tid == 1023) s_carry = c + incl;
        __syncthreads();
    }
    if (tid == 0) g_off[n] = s_carry;
}

__global__ void k_fill(const int* __restrict__ ei) {
    int e = blockIdx.x * blockDim.x + threadIdx.x;
    if (e >= ETOT) return;
    int src, dst;
    if (e < EIN) { src = ei[e]; dst = ei[EIN + e]; }
    else         { src = e - EIN; dst = e - EIN; }
    int pos = g_off[dst] + atomicAdd(&g_fill[dst], 1);
    g_src[pos] = src;
}

__global__ void k_clear() {
    int i = blockIdx.x * blockDim.x + threadIdx.x;
    if (i < NN) { g_deg[i] = 0; g_fill[i] = 0; }
}

// ---------------- tf32 tensor-core GEMM: C[M,N] = A[M,K] * B[N,K]^T ---------
#define SMS 20  // smem row stride in floats

__device__ __forceinline__ uint32_t f2tf32(float f) {
    uint32_t u;
    asm("cvt.rna.tf32.f32 %0, %1;" : "=r"(u) : "f"(f));
    return u;
}

__global__ __launch_bounds__(256, 1)
void k_gemm_tf32(const float* __restrict__ Ain, const float* __restrict__ B,
                 int M, int N, int K) {
    const float* A = Ain ? Ain : g_bufB;
    float* C = g_bufA;

    __shared__ float As[2][128 * SMS];
    __shared__ float Bs[2][128 * SMS];

    const int tid  = threadIdx.x;
    const int lane = tid & 31;
    const int wid  = tid >> 5;
    const int gid  = lane >> 2;
    const int tg   = lane & 3;
    const int wm   = (wid >> 2) * 64;
    const int wn   = (wid & 3) * 32;

    const int bm = blockIdx.y * 128;
    const int bn = blockIdx.x * 128;

    const int r0 = tid >> 2;
    const int kq = (tid & 3) * 4;

    float acc[4][4][4];
    #pragma unroll
    for (int mt = 0; mt < 4; mt++)
        #pragma unroll
        for (int nt = 0; nt < 4; nt++)
            #pragma unroll
            for (int i = 0; i < 4; i++) acc[mt][nt][i] = 0.f;

    const int KC = K >> 4;

    float4 ra0, ra1, rb0, rb1;
    {
        int am0 = bm + r0, am1 = bm + r0 + 64;
        ra0 = (am0 < M) ? *(const float4*)(A + (size_t)am0 * K + kq) : make_float4(0,0,0,0);
        ra1 = (am1 < M) ? *(const float4*)(A + (size_t)am1 * K + kq) : make_float4(0,0,0,0);
        rb0 = *(const float4*)(B + (size_t)(bn + r0) * K + kq);
        rb1 = *(const float4*)(B + (size_t)(bn + r0 + 64) * K + kq);
    }
    {
        float* ap = &As[0][r0 * SMS + kq];
        float* bp = &Bs[0][r0 * SMS + kq];
        ap[0]=__uint_as_float(f2tf32(ra0.x)); ap[1]=__uint_as_float(f2tf32(ra0.y));
        ap[2]=__uint_as_float(f2tf32(ra0.z)); ap[3]=__uint_as_float(f2tf32(ra0.w));
        ap[64*SMS+0]=__uint_as_float(f2tf32(ra1.x)); ap[64*SMS+1]=__uint_as_float(f2tf32(ra1.y));
        ap[64*SMS+2]=__uint_as_float(f2tf32(ra1.z)); ap[64*SMS+3]=__uint_as_float(f2tf32(ra1.w));
        bp[0]=__uint_as_float(f2tf32(rb0.x)); bp[1]=__uint_as_float(f2tf32(rb0.y));
        bp[2]=__uint_as_float(f2tf32(rb0.z)); bp[3]=__uint_as_float(f2tf32(rb0.w));
        bp[64*SMS+0]=__uint_as_float(f2tf32(rb1.x)); bp[64*SMS+1]=__uint_as_float(f2tf32(rb1.y));
        bp[64*SMS+2]=__uint_as_float(f2tf32(rb1.z)); bp[64*SMS+3]=__uint_as_float(f2tf32(rb1.w));
    }
    __syncthreads();

    for (int kc = 0; kc < KC; kc++) {
        if (kc + 1 < KC) {
            int koff = (kc + 1) * 16 + kq;
            int am0 = bm + r0, am1 = bm + r0 + 64;
            ra0 = (am0 < M) ? *(const float4*)(A + (size_t)am0 * K + koff) : make_float4(0,0,0,0);
            ra1 = (am1 < M) ? *(const float4*)(A + (size_t)am1 * K + koff) : make_float4(0,0,0,0);
            rb0 = *(const float4*)(B + (size_t)(bn + r0) * K + koff);
            rb1 = *(const float4*)(B + (size_t)(bn + r0 + 64) * K + koff);
        }

        const float* as = As[kc & 1];
        const float* bs = Bs[kc & 1];
        #pragma unroll
        for (int s = 0; s < 2; s++) {
            int kl = s * 8;
            uint32_t af[4][4], bf[4][2];
            #pragma unroll
            for (int mt = 0; mt < 4; mt++) {
                int m = wm + mt * 16 + gid;
                af[mt][0] = __float_as_uint(as[m * SMS + kl + tg]);
                af[mt][1] = __float_as_uint(as[(m + 8) * SMS + kl + tg]);
                af[mt][2] = __float_as_uint(as[m * SMS + kl + tg + 4]);
                af[mt][3] = __float_as_uint(as[(m + 8) * SMS + kl + tg + 4]);
            }
            #pragma unroll
            for (int nt = 0; nt < 4; nt++) {
                int n = wn + nt * 8 + gid;
                bf[nt][0] = __float_as_uint(bs[n * SMS + kl + tg]);
                bf[nt][1] = __float_as_uint(bs[n * SMS + kl + tg + 4]);
            }
            #pragma unroll
            for (int mt = 0; mt < 4; mt++)
                #pragma unroll
                for (int nt = 0; nt < 4; nt++) {
                    asm volatile(
                        "mma.sync.aligned.m16n8k8.row.col.f32.tf32.tf32.f32 "
                        "{%0,%1,%2,%3}, {%4,%5,%6,%7}, {%8,%9}, {%0,%1,%2,%3};"
                        : "+f"(acc[mt][nt][0]), "+f"(acc[mt][nt][1]),
                          "+f"(acc[mt][nt][2]), "+f"(acc[mt][nt][3])
                        : "r"(af[mt][0]), "r"(af[mt][1]), "r"(af[mt][2]), "r"(af[mt][3]),
                          "r"(bf[nt][0]), "r"(bf[nt][1]));
                }
        }

        __syncthreads();
        if (kc + 1 < KC) {
            float* ap = &As[(kc + 1) & 1][r0 * SMS + kq];
            float* bp = &Bs[(kc + 1) & 1][r0 * SMS + kq];
            ap[0]=__uint_as_float(f2tf32(ra0.x)); ap[1]=__uint_as_float(f2tf32(ra0.y));
            ap[2]=__uint_as_float(f2tf32(ra0.z)); ap[3]=__uint_as_float(f2tf32(ra0.w));
            ap[64*SMS+0]=__uint_as_float(f2tf32(ra1.x)); ap[64*SMS+1]=__uint_as_float(f2tf32(ra1.y));
            ap[64*SMS+2]=__uint_as_float(f2tf32(ra1.z)); ap[64*SMS+3]=__uint_as_float(f2tf32(ra1.w));
            bp[0]=__uint_as_float(f2tf32(rb0.x)); bp[1]=__uint_as_float(f2tf32(rb0.y));
            bp[2]=__uint_as_float(f2tf32(rb0.z)); bp[3]=__uint_as_float(f2tf32(rb0.w));
            bp[64*SMS+0]=__uint_as_float(f2tf32(rb1.x)); bp[64*SMS+1]=__uint_as_float(f2tf32(rb1.y));
            bp[64*SMS+2]=__uint_as_float(f2tf32(rb1.z)); bp[64*SMS+3]=__uint_as_float(f2tf32(rb1.w));
            __syncthreads();
        }
    }

    #pragma unroll
    for (int mt = 0; mt < 4; mt++) {
        int gm0 = bm + wm + mt * 16 + gid;
        int gm1 = gm0 + 8;
        #pragma unroll
        for (int nt = 0; nt < 4; nt++) {
            int gn = bn + wn + nt * 8 + tg * 2;
            if (gm0 < M)
                *(float2*)(C + (size_t)gm0 * N + gn) = make_float2(acc[mt][nt][0], acc[mt][nt][1]);
            if (gm1 < M)
                *(float2*)(C + (size_t)gm1 * N + gn) = make_float2(acc[mt][nt][2], acc[mt][nt][3]);
        }
    }
}

// ---------------- attention coefficients es/ed (float4) ---------------------
__global__ void k_attn(const float* __restrict__ as_, const float* __restrict__ ad_,
                       int Fout, int C) {
    int t = blockIdx.x * blockDim.x + threadIdx.x;
    if (t >= NN * 8) return;
    int n = t >> 3, hd = t & 7;
    const float4* hp = (const float4*)(g_bufA + (size_t)n * Fout + hd * C);
    const float4* ap = (const float4*)(as_ + hd * C);
    const float4* dp = (const float4*)(ad_ + hd * C);
    float s = 0.f, d = 0.f;
    int c4 = C >> 2;
    for (int c = 0; c < c4; c++) {
        float4 v = __ldg(hp + c);
        float4 a = __ldg(ap + c);
        float4 b = __ldg(dp + c);
        s += v.x * a.x + v.y * a.y + v.z * a.z + v.w * a.w;
        d += v.x * b.x + v.y * b.y + v.z * b.z + v.w * b.w;
    }
    g_es[t] = s;
    g_ed[t] = d;
}

// ---------------- edge softmax (warp per dst node, 2 passes) ----------------
// Writes UNNORMALIZED exp(e - max) to g_alpha and 1/sum to g_inv.
__global__ void k_softmax() {
    int w = (blockIdx.x * blockDim.x + threadIdx.x) >> 5;
    if (w >= NN) return;
    int lane = threadIdx.x & 31;
    int head = lane & 7, sub = lane >> 3;
    int beg = g_off[w];
    int deg = g_off[w + 1] - beg;
    float edv = g_ed[w * 8 + head];
    float mx = -3.0e38f;
    for (int i = sub; i < deg; i += 4) {
        int s = g_src[beg + i];
        float e = g_es[s * 8 + head] + edv;
        e = e > 0.f ? e : 0.2f * e;
        g_alpha[(beg + i) * 8 + head] = e;
        mx = fmaxf(mx, e);
    }
    mx = fmaxf(mx, __shfl_xor_sync(0xffffffffu, mx, 8));
    mx = fmaxf(mx, __shfl_xor_sync(0xffffffffu, mx, 16));
    float sm = 0.f;
    for (int i = sub; i < deg; i += 4) {
        float ex = __expf(g_alpha[(beg + i) * 8 + head] - mx);
        g_alpha[(beg + i) * 8 + head] = ex;
        sm += ex;
    }
    sm += __shfl_xor_sync(0xffffffffu, sm, 8);
    sm += __shfl_xor_sync(0xffffffffu, sm, 16);
    if (lane < 8) g_inv[w * 8 + lane] = 1.f / sm;
}

// ---------------- aggregation ------------------------------------------------
// SPLIT=2^LOG2S warps per node; each warp covers WR float4 per lane.
// Fout = WR * 128 * SPLIT. Normalization (g_inv) applied in epilogue.
template <int WR, int LOG2C, bool ELU, int LOG2S>
__global__ void k_agg(const float* __restrict__ bias) {
    int gw = (blockIdx.x * blockDim.x + threadIdx.x) >> 5;
    int node = gw >> LOG2S;
    if (node >= NN) return;
    int part = gw & ((1 << LOG2S) - 1);
    const int lane = threadIdx.x & 31;
    const int Fout = (WR * 128) << LOG2S;
    const int base = part * (WR * 128);
    int beg = g_off[node], end = g_off[node + 1];

    float4 acc[WR];
    #pragma unroll
    for (int r = 0; r < WR; r++) acc[r] = make_float4(0.f, 0.f, 0.f, 0.f);

    for (int i = beg; i < end; i++) {
        int s = g_src[i];
        float a8 = (lane < 8) ? g_alpha[i * 8 + lane] : 0.f;
        const float4* hp = (const float4*)(g_bufA + (size_t)s * Fout + base);
        #pragma unroll
        for (int r = 0; r < WR; r++) {
            int f = base + r * 128 + lane * 4;
            float al = __shfl_sync(0xffffffffu, a8, f >> LOG2C);
            float4 h4 = __ldg(hp + r * 32 + lane);
            acc[r].x = fmaf(al, h4.x, acc[r].x);
            acc[r].y = fmaf(al, h4.y, acc[r].y);
            acc[r].z = fmaf(al, h4.z, acc[r].z);
            acc[r].w = fmaf(al, h4.w, acc[r].w);
        }
    }

    float* op = g_bufB + (size_t)node * Fout;
    #pragma unroll
    for (int r = 0; r < WR; r++) {
        int f = base + r * 128 + lane * 4;
        float inv = g_inv[node * 8 + (f >> LOG2C)];
        float4 b4 = __ldg((const float4*)(bias + f));
        float4 v;
        v.x = fmaf(acc[r].x, inv, b4.x);
        v.y = fmaf(acc[r].y, inv, b4.y);
        v.z = fmaf(acc[r].z, inv, b4.z);
        v.w = fmaf(acc[r].w, inv, b4.w);
        if (ELU) {
            v.x = v.x > 0.f ? v.x : expm1f(v.x);
            v.y = v.y > 0.f ? v.y : expm1f(v.y);
            v.z = v.z > 0.f ? v.z : expm1f(v.z);
            v.w = v.w > 0.f ? v.w : expm1f(v.w);
        }
        *(float4*)(op + f) = v;
    }
}

// ---------------- pooling ----------------------------------------------------
__global__ void k_pool_init() {
    int i = blockIdx.x * blockDim.x + threadIdx.x;
    if (i < GMAX * 512) g_pool[i] = 0.f;
    if (i < GMAX) g_cnt[i] = 0.f;
}

__global__ void k_pool(const int* __restrict__ batch) {
    int f = threadIdx.x;
    int n0 = blockIdx.x * 512;
    int n1 = n0 + 512; if (n1 > NN) n1 = NN;
    if (n0 >= NN) return;
    float acc = 0.f;
    int cur = __ldg(&batch[n0]);
    for (int n = n0; n < n1; n++) {
        int b = __ldg(&batch[n]);
        if (b != cur) { atomicAdd(&g_pool[cur * 512 + f], acc); acc = 0.f; cur = b; }
        acc += g_bufB[(size_t)n * 512 + f];
    }
    atomicAdd(&g_pool[cur * 512 + f], acc);
}

__global__ void k_cnt(const int* __restrict__ batch) {
    int n = blockIdx.x * blockDim.x + threadIdx.x;
    if (n < NN) atomicAdd(&g_cnt[batch[n]], 1.f);
}

// ---------------- MLP head ---------------------------------------------------
__global__ void k_mlp1(const float* __restrict__ lw1, const float* __restrict__ lb1) {
    int t = blockIdx.x * blockDim.x + threadIdx.x;
    if (t >= GMAX * 32) return;
    int g = t >> 5, j = t & 31;
    float inv = 1.f / fmaxf(g_cnt[g], 1.f);
    const float* pp = g_pool + g * 512;
    const float* wp = lw1 + j * 512;
    float s = 0.f;
    for (int k = 0; k < 512; k++) s += pp[k] * __ldg(wp + k);
    s = s * inv + __ldg(lb1 + j);
    g_mlp[t] = s > 0.f ? s : expm1f(s);
}

__global__ void k_mlp2(const float* __restrict__ lw2, const float* __restrict__ lb2,
                       float* __restrict__ out) {
    int t = threadIdx.x;
    if (t >= GMAX * 2) return;
    int g = t >> 1, o = t & 1;
    const float* mp = g_mlp + g * 32;
    const float* wp = lw2 + o * 32;
    float s = 0.f;
    #pragma unroll
    for (int k = 0; k < 32; k++) s += mp[k] * __ldg(wp + k);
    out[t] = s + __ldg(lb2 + o);
}

// ---------------- launch -----------------------------------------------------
extern "C" void kernel_launch(void* const* d_in, const int* in_sizes, int n_in,
                              void* d_out, int out_size) {
    const float* x     = (const float*)d_in[0];
    const int*   ei    = (const int*)  d_in[1];
    const int*   batch = (const int*)  d_in[2];
    const float *W[4], *as_[4], *ad_[4], *bb[4];
    for (int l = 0; l < 4; l++) {
        W[l]   = (const float*)d_in[3 + l * 4];
        as_[l] = (const float*)d_in[4 + l * 4];
        ad_[l] = (const float*)d_in[5 + l * 4];
        bb[l]  = (const float*)d_in[6 + l * 4];
    }
    const float* lw1 = (const float*)d_in[19];
    const float* lb1 = (const float*)d_in[20];
    const float* lw2 = (const float*)d_in[21];
    const float* lb2 = (const float*)d_in[22];
    float* out = (float*)d_out;

    // CSR build (deg/fill are zero: static init on first call, k_clear after)
    k_count<<<(ETOT + 255) / 256, 256>>>(ei);
    k_scan <<<1, 1024>>>();
    k_fill <<<(ETOT + 255) / 256, 256>>>(ei);

    const int Fo[4] = {512, 256, 128, 512};
    const int Cc[4] = {64, 32, 16, 64};
    const int Fin[4] = {128, 512, 256, 128};

    for (int l = 0; l < 4; l++) {
        const float* in = (l == 0) ? x : nullptr;  // nullptr => g_bufB
        dim3 gg(Fo[l] / 128, (NN + 127) / 128);
        k_gemm_tf32<<<gg, 256>>>(in, W[l], NN, Fo[l], Fin[l]);
        k_attn<<<(NN * 8 + 255) / 256, 256>>>(as_[l], ad_[l], Fo[l], Cc[l]);
        k_softmax<<<(NN + 7) / 8, 256>>>();
        if (l == 0) {
            int nb = (NN * 2 * 32 + 255) / 256;
            k_agg<2, 6, true, 1><<<nb, 256>>>(bb[l]);
        } else if (l == 1) {
            int nb = (NN * 2 * 32 + 255) / 256;
            k_agg<1, 5, true, 1><<<nb, 256>>>(bb[l]);
        } else if (l == 2) {
            int nb = (NN * 32 + 255) / 256;
            k_agg<1, 4, true, 0><<<nb, 256>>>(bb[l]);
        } else {
            int nb = (NN * 2 * 32 + 255) / 256;
            k_agg<2, 6, false, 1><<<nb, 256>>>(bb[l]);
        }
    }

    k_pool_init<<<(GMAX * 512 + 255) / 256, 256>>>();
    k_pool<<<(NN + 511) / 512, 512>>>(batch);
    k_cnt <<<(NN + 255) / 256, 256>>>(batch);
    k_mlp1<<<8, 256>>>(lw1, lb1);
    k_mlp2<<<1, 128>>>(lw2, lb2, out);

    // re-zero CSR scratch for the next replay
    k_clear<<<(NN + 255) / 256, 256>>>();
}

// round 4
// speedup vs baseline: 1.6395x; 1.1398x over previous
#include <cuda_runtime.h>
#include <math.h>
#include <stdint.h>

#define NN    50000
#define EIN   800000
#define ETOT  850000
#define GMAX  64

// ---------------- scratch (device globals; zero-initialized at load) -------
__device__ int   g_deg[NN];
__device__ int   g_off[NN + 1];
__device__ int   g_fill[NN];
__device__ int   g_src[ETOT];
__device__ float g_es[NN * 8];
__device__ float g_ed[NN * 8];
__device__ float g_inv[NN * 8];
__device__ float g_alpha[ETOT * 8];
__device__ float g_bufA[NN * 512];      // GEMM output h (per layer)
__device__ float g_bufB[NN * 512];      // agg output (tf32-rounded for l0-2)
__device__ float g_xr[NN * 128];        // tf32-rounded x
__device__ float g_wr[294912];          // tf32-rounded W1..W4 concatenated
__device__ float g_pool[GMAX * 512];
__device__ float g_cnt[GMAX];
__device__ float g_mlp[GMAX * 32];

__device__ __forceinline__ float tf32r(float f) {
    uint32_t u;
    asm("cvt.rna.tf32.f32 %0, %1;" : "=r"(u) : "f"(f));
    return __uint_as_float(u);
}

// ---------------- operand rounding ------------------------------------------
__global__ void k_round(const float* __restrict__ s, float* __restrict__ d, int n4) {
    int i = blockIdx.x * blockDim.x + threadIdx.x;
    if (i >= n4) return;
    float4 v = ((const float4*)s)[i];
    v.x = tf32r(v.x); v.y = tf32r(v.y); v.z = tf32r(v.z); v.w = tf32r(v.w);
    ((float4*)d)[i] = v;
}

// ---------------- CSR build ------------------------------------------------
__global__ void k_count(const int* __restrict__ ei) {
    int e = blockIdx.x * blockDim.x + threadIdx.x;
    if (e >= ETOT) return;
    int dst = (e < EIN) ? ei[EIN + e] : (e - EIN);
    atomicAdd(&g_deg[dst], 1);
}

__global__ void k_scan() {
    __shared__ int wsum[32];
    __shared__ int s_carry;
    int tid = threadIdx.x;
    if (tid == 0) s_carry = 0;
    __syncthreads();
    const int n = NN;
    int ntiles = (n + 1023) / 1024;
    for (int t = 0; t < ntiles; t++) {
        int idx = t * 1024 + tid;
        int v = (idx < n) ? g_deg[idx] : 0;
        int x = v;
        #pragma unroll
        for (int off = 1; off < 32; off <<= 1) {
            int y = __shfl_up_sync(0xffffffffu, x, off);
            if ((tid & 31) >= off) x += y;
        }
        if ((tid & 31) == 31) wsum[tid >> 5] = x;
        __syncthreads();
        if (tid < 32) {
            int w = wsum[tid];
            #pragma unroll
            for (int off = 1; off < 32; off <<= 1) {
                int y = __shfl_up_sync(0xffffffffu, w, off);
                if (tid >= off) w += y;
            }
            wsum[tid] = w;
        }
        __syncthreads();
        int incl = x + ((tid >= 32) ? wsum[(tid >> 5) - 1] : 0);
        int c = s_carry;
        if (idx < n) g_off[idx] = c + incl - v;
        __syncthreads();
        if (tid == 1023) s_carry = c + incl;
        __syncthreads();
    }
    if (tid == 0) g_off[n] = s_carry;
}

__global__ void k_fill(const int* __restrict__ ei) {
    int e = blockIdx.x * blockDim.x + threadIdx.x;
    if (e >= ETOT) return;
    int src, dst;
    if (e < EIN) { src = ei[e]; dst = ei[EIN + e]; }
    else         { src = e - EIN; dst = e - EIN; }
    int pos = g_off[dst] + atomicAdd(&g_fill[dst], 1);
    g_src[pos] = src;
}

__global__ void k_clear() {
    int i = blockIdx.x * blockDim.x + threadIdx.x;
    if (i < NN) { g_deg[i] = 0; g_fill[i] = 0; }
}

// ---------------- tf32 tensor-core GEMM (cp.async, pre-rounded inputs) ------
// C[M,N] = A[M,K] * B[N,K]^T, 128x128x16 tiles, 2-stage LDGSTS pipeline.
#define SMS 20  // smem row stride in floats

__device__ __forceinline__ void cpa16(uint32_t dst, const void* src, bool p) {
    int sz = p ? 16 : 0;
    asm volatile("cp.async.cg.shared.global [%0], [%1], 16, %2;"
                 :: "r"(dst), "l"(src), "r"(sz));
}

__global__ __launch_bounds__(256, 2)
void k_gemm_tc(const float* __restrict__ Ain, const float* __restrict__ B,
               int M, int N, int K) {
    const float* A = Ain ? Ain : g_bufB;
    float* C = g_bufA;

    __shared__ float As[2][128 * SMS];
    __shared__ float Bs[2][128 * SMS];

    const int tid  = threadIdx.x;
    const int lane = tid & 31;
    const int wid  = tid >> 5;
    const int gid  = lane >> 2;
    const int tg   = lane & 3;
    const int wm   = (wid >> 2) * 64;
    const int wn   = (wid & 3) * 32;

    const int bm = blockIdx.y * 128;
    const int bn = blockIdx.x * 128;

    const int r0 = tid >> 2;
    const int kq = (tid & 3) * 4;

    const int am0 = bm + r0, am1 = bm + r0 + 64;
    const bool p0 = am0 < M, p1 = am1 < M;
    const float* arow0 = A + (size_t)(p0 ? am0 : 0) * K + kq;
    const float* arow1 = A + (size_t)(p1 ? am1 : 0) * K + kq;
    const float* brow0 = B + (size_t)(bn + r0) * K + kq;
    const float* brow1 = B + (size_t)(bn + r0 + 64) * K + kq;

    uint32_t as_base = (uint32_t)__cvta_generic_to_shared(&As[0][0]) + (r0 * SMS + kq) * 4;
    uint32_t bs_base = (uint32_t)__cvta_generic_to_shared(&Bs[0][0]) + (r0 * SMS + kq) * 4;
    const uint32_t stage = 128 * SMS * 4;
    const uint32_t half  = 64 * SMS * 4;

    float acc[4][4][4];
    #pragma unroll
    for (int mt = 0; mt < 4; mt++)
        #pragma unroll
        for (int nt = 0; nt < 4; nt++)
            #pragma unroll
            for (int i = 0; i < 4; i++) acc[mt][nt][i] = 0.f;

    const int KC = K >> 4;

    auto issue = [&](int kc, int buf) {
        int ko = kc * 16;
        cpa16(as_base + buf * stage,        arow0 + ko, p0);
        cpa16(as_base + buf * stage + half, arow1 + ko, p1);
        cpa16(bs_base + buf * stage,        brow0 + ko, true);
        cpa16(bs_base + buf * stage + half, brow1 + ko, true);
        asm volatile("cp.async.commit_group;");
    };

    issue(0, 0);
    asm volatile("cp.async.wait_group 0;");
    __syncthreads();

    for (int kc = 0; kc < KC; kc++) {
        int b = kc & 1;
        if (kc + 1 < KC) issue(kc + 1, 1 - b);

        const float* as = As[b];
        const float* bs = Bs[b];
        #pragma unroll
        for (int s = 0; s < 2; s++) {
            int kl = s * 8;
            uint32_t af[4][4], bf[4][2];
            #pragma unroll
            for (int mt = 0; mt < 4; mt++) {
                int m = wm + mt * 16 + gid;
                af[mt][0] = __float_as_uint(as[m * SMS + kl + tg]);
                af[mt][1] = __float_as_uint(as[(m + 8) * SMS + kl + tg]);
                af[mt][2] = __float_as_uint(as[m * SMS + kl + tg + 4]);
                af[mt][3] = __float_as_uint(as[(m + 8) * SMS + kl + tg + 4]);
            }
            #pragma unroll
            for (int nt = 0; nt < 4; nt++) {
                int n = wn + nt * 8 + gid;
                bf[nt][0] = __float_as_uint(bs[n * SMS + kl + tg]);
                bf[nt][1] = __float_as_uint(bs[n * SMS + kl + tg + 4]);
            }
            #pragma unroll
            for (int mt = 0; mt < 4; mt++)
                #pragma unroll
                for (int nt = 0; nt < 4; nt++) {
                    asm volatile(
                        "mma.sync.aligned.m16n8k8.row.col.f32.tf32.tf32.f32 "
                        "{%0,%1,%2,%3}, {%4,%5,%6,%7}, {%8,%9}, {%0,%1,%2,%3};"
                        : "+f"(acc[mt][nt][0]), "+f"(acc[mt][nt][1]),
                          "+f"(acc[mt][nt][2]), "+f"(acc[mt][nt][3])
                        : "r"(af[mt][0]), "r"(af[mt][1]), "r"(af[mt][2]), "r"(af[mt][3]),
                          "r"(bf[nt][0]), "r"(bf[nt][1]));
                }
        }

        if (kc + 1 < KC) {
            asm volatile("cp.async.wait_group 0;");
            __syncthreads();
        }
    }

    #pragma unroll
    for (int mt = 0; mt < 4; mt++) {
        int gm0 = bm + wm + mt * 16 + gid;
        int gm1 = gm0 + 8;
        #pragma unroll
        for (int nt = 0; nt < 4; nt++) {
            int gn = bn + wn + nt * 8 + tg * 2;
            if (gm0 < M)
                *(float2*)(C + (size_t)gm0 * N + gn) = make_float2(acc[mt][nt][0], acc[mt][nt][1]);
            if (gm1 < M)
                *(float2*)(C + (size_t)gm1 * N + gn) = make_float2(acc[mt][nt][2], acc[mt][nt][3]);
        }
    }
}

// ---------------- attention coefficients es/ed (float4) ---------------------
__global__ void k_attn(const float* __restrict__ as_, const float* __restrict__ ad_,
                       int Fout, int C) {
    int t = blockIdx.x * blockDim.x + threadIdx.x;
    if (t >= NN * 8) return;
    int n = t >> 3, hd = t & 7;
    const float4* hp = (const float4*)(g_bufA + (size_t)n * Fout + hd * C);
    const float4* ap = (const float4*)(as_ + hd * C);
    const float4* dp = (const float4*)(ad_ + hd * C);
    float s = 0.f, d = 0.f;
    int c4 = C >> 2;
    for (int c = 0; c < c4; c++) {
        float4 v = __ldg(hp + c);
        float4 a = __ldg(ap + c);
        float4 b = __ldg(dp + c);
        s += v.x * a.x + v.y * a.y + v.z * a.z + v.w * a.w;
        d += v.x * b.x + v.y * b.y + v.z * b.z + v.w * b.w;
    }
    g_es[t] = s;
    g_ed[t] = d;
}

// ---------------- edge softmax (warp per dst node) ---------------------------
__global__ void k_softmax() {
    int w = (blockIdx.x * blockDim.x + threadIdx.x) >> 5;
    if (w >= NN) return;
    int lane = threadIdx.x & 31;
    int head = lane & 7, sub = lane >> 3;
    int beg = g_off[w];
    int deg = g_off[w + 1] - beg;
    float edv = g_ed[w * 8 + head];
    float mx = -3.0e38f;
    for (int i = sub; i < deg; i += 4) {
        int s = g_src[beg + i];
        float e = g_es[s * 8 + head] + edv;
        e = e > 0.f ? e : 0.2f * e;
        g_alpha[(beg + i) * 8 + head] = e;
        mx = fmaxf(mx, e);
    }
    mx = fmaxf(mx, __shfl_xor_sync(0xffffffffu, mx, 8));
    mx = fmaxf(mx, __shfl_xor_sync(0xffffffffu, mx, 16));
    float sm = 0.f;
    for (int i = sub; i < deg; i += 4) {
        float ex = __expf(g_alpha[(beg + i) * 8 + head] - mx);
        g_alpha[(beg + i) * 8 + head] = ex;
        sm += ex;
    }
    sm += __shfl_xor_sync(0xffffffffu, sm, 8);
    sm += __shfl_xor_sync(0xffffffffu, sm, 16);
    if (lane < 8) g_inv[w * 8 + lane] = 1.f / sm;
}

// ---------------- aggregation (2-edge unrolled) ------------------------------
// RND: write tf32-rounded output (layers whose output feeds a GEMM).
template <int WR, int LOG2C, bool ELU, int LOG2S, bool RND>
__global__ void k_agg(const float* __restrict__ bias) {
    int gw = (blockIdx.x * blockDim.x + threadIdx.x) >> 5;
    int node = gw >> LOG2S;
    if (node >= NN) return;
    int part = gw & ((1 << LOG2S) - 1);
    const int lane = threadIdx.x & 31;
    const int Fout = (WR * 128) << LOG2S;
    const int base = part * (WR * 128);
    int beg = g_off[node], end = g_off[node + 1];

    float4 acc[WR];
    #pragma unroll
    for (int r = 0; r < WR; r++) acc[r] = make_float4(0.f, 0.f, 0.f, 0.f);

    int i = beg;
    for (; i + 2 <= end; i += 2) {
        int s0 = g_src[i], s1 = g_src[i + 1];
        float a0 = (lane < 8) ? g_alpha[i * 8 + lane] : 0.f;
        float a1 = (lane < 8) ? g_alpha[i * 8 + 8 + lane] : 0.f;
        const float4* h0 = (const float4*)(g_bufA + (size_t)s0 * Fout + base);
        const float4* h1 = (const float4*)(g_bufA + (size_t)s1 * Fout + base);
        #pragma unroll
        for (int r = 0; r < WR; r++) {
            int f = base + r * 128 + lane * 4;
            int hh = f >> LOG2C;
            float4 v0 = __ldg(h0 + r * 32 + lane);
            float4 v1 = __ldg(h1 + r * 32 + lane);
            float al0 = __shfl_sync(0xffffffffu, a0, hh);
            float al1 = __shfl_sync(0xffffffffu, a1, hh);
            acc[r].x = fmaf(al0, v0.x, fmaf(al1, v1.x, acc[r].x));
            acc[r].y = fmaf(al0, v0.y, fmaf(al1, v1.y, acc[r].y));
            acc[r].z = fmaf(al0, v0.z, fmaf(al1, v1.z, acc[r].z));
            acc[r].w = fmaf(al0, v0.w, fmaf(al1, v1.w, acc[r].w));
        }
    }
    if (i < end) {
        int s0 = g_src[i];
        float a0 = (lane < 8) ? g_alpha[i * 8 + lane] : 0.f;
        const float4* h0 = (const float4*)(g_bufA + (size_t)s0 * Fout + base);
        #pragma unroll
        for (int r = 0; r < WR; r++) {
            int f = base + r * 128 + lane * 4;
            float al0 = __shfl_sync(0xffffffffu, a0, f >> LOG2C);
            float4 v0 = __ldg(h0 + r * 32 + lane);
            acc[r].x = fmaf(al0, v0.x, acc[r].x);
            acc[r].y = fmaf(al0, v0.y, acc[r].y);
            acc[r].z = fmaf(al0, v0.z, acc[r].z);
            acc[r].w = fmaf(al0, v0.w, acc[r].w);
        }
    }

    float* op = g_bufB + (size_t)node * Fout;
    #pragma unroll
    for (int r = 0; r < WR; r++) {
        int f = base + r * 128 + lane * 4;
        float inv = g_inv[node * 8 + (f >> LOG2C)];
        float4 b4 = __ldg((const float4*)(bias + f));
        float4 v;
        v.x = fmaf(acc[r].x, inv, b4.x);
        v.y = fmaf(acc[r].y, inv, b4.y);
        v.z = fmaf(acc[r].z, inv, b4.z);
        v.w = fmaf(acc[r].w, inv, b4.w);
        if (ELU) {
            v.x = v.x > 0.f ? v.x : expm1f(v.x);
            v.y = v.y > 0.f ? v.y : expm1f(v.y);
            v.z = v.z > 0.f ? v.z : expm1f(v.z);
            v.w = v.w > 0.f ? v.w : expm1f(v.w);
        }
        if (RND) {
            v.x = tf32r(v.x); v.y = tf32r(v.y);
            v.z = tf32r(v.z); v.w = tf32r(v.w);
        }
        *(float4*)(op + f) = v;
    }
}

// ---------------- pooling ----------------------------------------------------
__global__ void k_pool_init() {
    int i = blockIdx.x * blockDim.x + threadIdx.x;
    if (i < GMAX * 512) g_pool[i] = 0.f;
    if (i < GMAX) g_cnt[i] = 0.f;
}

__global__ void k_pool(const int* __restrict__ batch) {
    int f = threadIdx.x;
    int n0 = blockIdx.x * 512;
    int n1 = n0 + 512; if (n1 > NN) n1 = NN;
    if (n0 >= NN) return;
    float acc = 0.f;
    int cur = __ldg(&batch[n0]);
    for (int n = n0; n < n1; n++) {
        int b = __ldg(&batch[n]);
        if (b != cur) { atomicAdd(&g_pool[cur * 512 + f], acc); acc = 0.f; cur = b; }
        acc += g_bufB[(size_t)n * 512 + f];
    }
    atomicAdd(&g_pool[cur * 512 + f], acc);
}

__global__ void k_cnt(const int* __restrict__ batch) {
    int n = blockIdx.x * blockDim.x + threadIdx.x;
    if (n < NN) atomicAdd(&g_cnt[batch[n]], 1.f);
}

// ---------------- MLP head ---------------------------------------------------
__global__ void k_mlp1(const float* __restrict__ lw1, const float* __restrict__ lb1) {
    int t = blockIdx.x * blockDim.x + threadIdx.x;
    if (t >= GMAX * 32) return;
    int g = t >> 5, j = t & 31;
    float inv = 1.f / fmaxf(g_cnt[g], 1.f);
    const float* pp = g_pool + g * 512;
    const float* wp = lw1 + j * 512;
    float s = 0.f;
    for (int k = 0; k < 512; k++) s += pp[k] * __ldg(wp + k);
    s = s * inv + __ldg(lb1 + j);
    g_mlp[t] = s > 0.f ? s : expm1f(s);
}

__global__ void k_mlp2(const float* __restrict__ lw2, const float* __restrict__ lb2,
                       float* __restrict__ out) {
    int t = threadIdx.x;
    if (t >= GMAX * 2) return;
    int g = t >> 1, o = t & 1;
    const float* mp = g_mlp + g * 32;
    const float* wp = lw2 + o * 32;
    float s = 0.f;
    #pragma unroll
    for (int k = 0; k < 32; k++) s += mp[k] * __ldg(wp + k);
    out[t] = s + __ldg(lb2 + o);
}

// ---------------- launch -----------------------------------------------------
extern "C" void kernel_launch(void* const* d_in, const int* in_sizes, int n_in,
                              void* d_out, int out_size) {
    const float* x     = (const float*)d_in[0];
    const int*   ei    = (const int*)  d_in[1];
    const int*   batch = (const int*)  d_in[2];
    const float *W[4], *as_[4], *ad_[4], *bb[4];
    for (int l = 0; l < 4; l++) {
        W[l]   = (const float*)d_in[3 + l * 4];
        as_[l] = (const float*)d_in[4 + l * 4];
        ad_[l] = (const float*)d_in[5 + l * 4];
        bb[l]  = (const float*)d_in[6 + l * 4];
    }
    const float* lw1 = (const float*)d_in[19];
    const float* lb1 = (const float*)d_in[20];
    const float* lw2 = (const float*)d_in[21];
    const float* lb2 = (const float*)d_in[22];
    float* out = (float*)d_out;

    // round operands to tf32 once
    const int wsz[4] = {512 * 128, 256 * 512, 128 * 256, 512 * 128};
    const int woff[4] = {0, 65536, 196608, 229376};
    float* wr_base;
    cudaGetSymbolAddress((void**)&wr_base, g_wr);
    float* xr_base;
    cudaGetSymbolAddress((void**)&xr_base, g_xr);
    k_round<<<(NN * 128 / 4 + 255) / 256, 256>>>(x, xr_base, NN * 128 / 4);
    for (int l = 0; l < 4; l++)
        k_round<<<(wsz[l] / 4 + 255) / 256, 256>>>(W[l], wr_base + woff[l], wsz[l] / 4);

    // CSR build
    k_count<<<(ETOT + 255) / 256, 256>>>(ei);
    k_scan <<<1, 1024>>>();
    k_fill <<<(ETOT + 255) / 256, 256>>>(ei);

    const int Fo[4]  = {512, 256, 128, 512};
    const int Cc[4]  = {64, 32, 16, 64};
    const int Fin[4] = {128, 512, 256, 128};

    for (int l = 0; l < 4; l++) {
        const float* in = (l == 0) ? xr_base : nullptr;  // nullptr => g_bufB
        dim3 gg(Fo[l] / 128, (NN + 127) / 128);
        k_gemm_tc<<<gg, 256>>>(in, wr_base + woff[l], NN, Fo[l], Fin[l]);
        k_attn<<<(NN * 8 + 255) / 256, 256>>>(as_[l], ad_[l], Fo[l], Cc[l]);
        k_softmax<<<(NN + 7) / 8, 256>>>();
        if (l == 0) {
            int nb = (NN * 2 * 32 + 255) / 256;
            k_agg<2, 6, true, 1, true><<<nb, 256>>>(bb[l]);
        } else if (l == 1) {
            int nb = (NN * 2 * 32 + 255) / 256;
            k_agg<1, 5, true, 1, true><<<nb, 256>>>(bb[l]);
        } else if (l == 2) {
            int nb = (NN * 32 + 255) / 256;
            k_agg<1, 4, true, 0, true><<<nb, 256>>>(bb[l]);
        } else {
            int nb = (NN * 2 * 32 + 255) / 256;
            k_agg<2, 6, false, 1, false><<<nb, 256>>>(bb[l]);
        }
    }

    k_pool_init<<<(GMAX * 512 + 255) / 256, 256>>>();
    k_pool<<<(NN + 511) / 512, 512>>>(batch);
    k_cnt <<<(NN + 255) / 256, 256>>>(batch);
    k_mlp1<<<8, 256>>>(lw1, lb1);
    k_mlp2<<<1, 128>>>(lw2, lb2, out);

    // re-zero CSR scratch for the next replay
    k_clear<<<(NN + 255) / 256, 256>>>();
}

// round 5
// speedup vs baseline: 2.0795x; 1.2684x over previous
#include <cuda_runtime.h>
#include <cuda_fp16.h>
#include <math.h>
#include <stdint.h>

#define NN    50000
#define EIN   800000
#define ETOT  850000
#define GMAX  64

// ---------------- scratch (device globals; zero-initialized at load) -------
__device__ int    g_deg[NN];
__device__ int    g_off[NN + 1];
__device__ int    g_fill[NN];
__device__ int    g_src[ETOT];
__device__ float  g_es[NN * 8];
__device__ float  g_ed[NN * 8];
__device__ float  g_inv[NN * 8];
__device__ float  g_alpha[ETOT * 8];
__device__ __half g_h16[NN * 512];      // GEMM output h (fp16)
__device__ float  g_bufB[NN * 512];     // agg output (tf32-rounded for l0-2)
__device__ float  g_xr[NN * 128];       // tf32-rounded x
__device__ float  g_wr[294912];         // tf32-rounded W1..W4 concatenated
__device__ float  g_pool[GMAX * 512];
__device__ float  g_cnt[GMAX];
__device__ float  g_mlp[GMAX * 32];

__device__ __forceinline__ float tf32r(float f) {
    uint32_t u;
    asm("cvt.rna.tf32.f32 %0, %1;" : "=r"(u) : "f"(f));
    return __uint_as_float(u);
}

// ---------------- fused operand rounding (x + W1..W4 in one kernel) --------
#define X4   (NN * 128 / 4)            // 1,600,000 float4
#define W4T  (294912 / 4)              // 73,728 float4
__global__ void k_round_all(const float* __restrict__ x,
                            const float* __restrict__ w1, const float* __restrict__ w2,
                            const float* __restrict__ w3, const float* __restrict__ w4) {
    int i = blockIdx.x * blockDim.x + threadIdx.x;
    const float4* s;
    float4* d;
    if (i < X4) {
        s = (const float4*)x + i;
        d = (float4*)g_xr + i;
    } else {
        int j = i - X4;
        if (j >= W4T) return;
        d = (float4*)g_wr + j;
        if      (j < 16384) s = (const float4*)w1 + j;
        else if (j < 49152) s = (const float4*)w2 + (j - 16384);
        else if (j < 57344) s = (const float4*)w3 + (j - 49152);
        else                s = (const float4*)w4 + (j - 57344);
    }
    float4 v = *s;
    v.x = tf32r(v.x); v.y = tf32r(v.y); v.z = tf32r(v.z); v.w = tf32r(v.w);
    *d = v;
}

__global__ void k_zero_att() {
    int i = blockIdx.x * blockDim.x + threadIdx.x;
    if (i < NN * 8) { g_es[i] = 0.f; g_ed[i] = 0.f; }
}

// ---------------- CSR build ------------------------------------------------
__global__ void k_count(const int* __restrict__ ei) {
    int e = blockIdx.x * blockDim.x + threadIdx.x;
    if (e >= ETOT) return;
    int dst = (e < EIN) ? ei[EIN + e] : (e - EIN);
    atomicAdd(&g_deg[dst], 1);
}

__global__ void k_scan() {
    __shared__ int wsum[32];
    __shared__ int s_carry;
    int tid = threadIdx.x;
    if (tid == 0) s_carry = 0;
    __syncthreads();
    const int n = NN;
    int ntiles = (n + 1023) / 1024;
    for (int t = 0; t < ntiles; t++) {
        int idx = t * 1024 + tid;
        int v = (idx < n) ? g_deg[idx] : 0;
        int x = v;
        #pragma unroll
        for (int off = 1; off < 32; off <<= 1) {
            int y = __shfl_up_sync(0xffffffffu, x, off);
            if ((tid & 31) >= off) x += y;
        }
        if ((tid & 31) == 31) wsum[tid >> 5] = x;
        __syncthreads();
        if (tid < 32) {
            int w = wsum[tid];
            #pragma unroll
            for (int off = 1; off < 32; off <<= 1) {
                int y = __shfl_up_sync(0xffffffffu, w, off);
                if (tid >= off) w += y;
            }
            wsum[tid] = w;
        }
        __syncthreads();
        int incl = x + ((tid >= 32) ? wsum[(tid >> 5) - 1] : 0);
        int c = s_carry;
        if (idx < n) g_off[idx] = c + incl - v;
        __syncthreads();
        if (tid == 1023) s_carry = c + incl;
        __syncthreads();
    }
    if (tid == 0) g_off[n] = s_carry;
}

__global__ void k_fill(const int* __restrict__ ei) {
    int e = blockIdx.x * blockDim.x + threadIdx.x;
    if (e >= ETOT) return;
    int src, dst;
    if (e < EIN) { src = ei[e]; dst = ei[EIN + e]; }
    else         { src = e - EIN; dst = e - EIN; }
    int pos = g_off[dst] + atomicAdd(&g_fill[dst], 1);
    g_src[pos] = src;
}

// ---------------- tf32 GEMM + fused attention epilogue ----------------------
// C[M,N] = A[M,K] * B[N,K]^T; writes h as fp16 to g_h16 and accumulates
// es/ed (per node,head) from fp32 accumulators via atomics.
#define SMS 20  // smem row stride in floats

__device__ __forceinline__ void cpa16(uint32_t dst, const void* src, bool p) {
    int sz = p ? 16 : 0;
    asm volatile("cp.async.cg.shared.global [%0], [%1], 16, %2;"
                 :: "r"(dst), "l"(src), "r"(sz));
}

__global__ __launch_bounds__(256, 2)
void k_gemm_tc(const float* __restrict__ Ain, const float* __restrict__ B,
               const float* __restrict__ as_, const float* __restrict__ ad_,
               int M, int N, int K, int C) {
    const float* A = Ain ? Ain : g_bufB;

    __shared__ float As[2][128 * SMS];
    __shared__ float Bs[2][128 * SMS];

    const int tid  = threadIdx.x;
    const int lane = tid & 31;
    const int wid  = tid >> 5;
    const int gid  = lane >> 2;
    const int tg   = lane & 3;
    const int wm   = (wid >> 2) * 64;
    const int wn   = (wid & 3) * 32;

    const int bm = blockIdx.y * 128;
    const int bn = blockIdx.x * 128;

    const int r0 = tid >> 2;
    const int kq = (tid & 3) * 4;

    const int am0 = bm + r0, am1 = bm + r0 + 64;
    const bool p0 = am0 < M, p1 = am1 < M;
    const float* arow0 = A + (size_t)(p0 ? am0 : 0) * K + kq;
    const float* arow1 = A + (size_t)(p1 ? am1 : 0) * K + kq;
    const float* brow0 = B + (size_t)(bn + r0) * K + kq;
    const float* brow1 = B + (size_t)(bn + r0 + 64) * K + kq;

    uint32_t as_base = (uint32_t)__cvta_generic_to_shared(&As[0][0]) + (r0 * SMS + kq) * 4;
    uint32_t bs_base = (uint32_t)__cvta_generic_to_shared(&Bs[0][0]) + (r0 * SMS + kq) * 4;
    const uint32_t stage = 128 * SMS * 4;
    const uint32_t half_ = 64 * SMS * 4;

    float acc[4][4][4];
    #pragma unroll
    for (int mt = 0; mt < 4; mt++)
        #pragma unroll
        for (int nt = 0; nt < 4; nt++)
            #pragma unroll
            for (int i = 0; i < 4; i++) acc[mt][nt][i] = 0.f;

    const int KC = K >> 4;

    auto issue = [&](int kc, int buf) {
        int ko = kc * 16;
        cpa16(as_base + buf * stage,         arow0 + ko, p0);
        cpa16(as_base + buf * stage + half_, arow1 + ko, p1);
        cpa16(bs_base + buf * stage,         brow0 + ko, true);
        cpa16(bs_base + buf * stage + half_, brow1 + ko, true);
        asm volatile("cp.async.commit_group;");
    };

    issue(0, 0);
    asm volatile("cp.async.wait_group 0;");
    __syncthreads();

    for (int kc = 0; kc < KC; kc++) {
        int b = kc & 1;
        if (kc + 1 < KC) issue(kc + 1, 1 - b);

        const float* as = As[b];
        const float* bs = Bs[b];
        #pragma unroll
        for (int s = 0; s < 2; s++) {
            int kl = s * 8;
            uint32_t af[4][4], bf[4][2];
            #pragma unroll
            for (int mt = 0; mt < 4; mt++) {
                int m = wm + mt * 16 + gid;
                af[mt][0] = __float_as_uint(as[m * SMS + kl + tg]);
                af[mt][1] = __float_as_uint(as[(m + 8) * SMS + kl + tg]);
                af[mt][2] = __float_as_uint(as[m * SMS + kl + tg + 4]);
                af[mt][3] = __float_as_uint(as[(m + 8) * SMS + kl + tg + 4]);
            }
            #pragma unroll
            for (int nt = 0; nt < 4; nt++) {
                int n = wn + nt * 8 + gid;
                bf[nt][0] = __float_as_uint(bs[n * SMS + kl + tg]);
                bf[nt][1] = __float_as_uint(bs[n * SMS + kl + tg + 4]);
            }
            #pragma unroll
            for (int mt = 0; mt < 4; mt++)
                #pragma unroll
                for (int nt = 0; nt < 4; nt++) {
                    asm volatile(
                        "mma.sync.aligned.m16n8k8.row.col.f32.tf32.tf32.f32 "
                        "{%0,%1,%2,%3}, {%4,%5,%6,%7}, {%8,%9}, {%0,%1,%2,%3};"
                        : "+f"(acc[mt][nt][0]), "+f"(acc[mt][nt][1]),
                          "+f"(acc[mt][nt][2]), "+f"(acc[mt][nt][3])
                        : "r"(af[mt][0]), "r"(af[mt][1]), "r"(af[mt][2]), "r"(af[mt][3]),
                          "r"(bf[nt][0]), "r"(bf[nt][1]));
                }
        }

        if (kc + 1 < KC) {
            asm volatile("cp.async.wait_group 0;");
            __syncthreads();
        }
    }

    // ---- epilogue 1: store h as fp16 ----
    #pragma unroll
    for (int mt = 0; mt < 4; mt++) {
        int gm0 = bm + wm + mt * 16 + gid;
        int gm1 = gm0 + 8;
        #pragma unroll
        for (int nt = 0; nt < 4; nt++) {
            int gn = bn + wn + nt * 8 + tg * 2;
            if (gm0 < M)
                *(__half2*)(g_h16 + (size_t)gm0 * N + gn) =
                    __floats2half2_rn(acc[mt][nt][0], acc[mt][nt][1]);
            if (gm1 < M)
                *(__half2*)(g_h16 + (size_t)gm1 * N + gn) =
                    __floats2half2_rn(acc[mt][nt][2], acc[mt][nt][3]);
        }
    }

    // ---- epilogue 2: fused attention partials (fp32 exact) ----
    float av[4][2], dv[4][2];
    #pragma unroll
    for (int nt = 0; nt < 4; nt++) {
        int gc = bn + wn + nt * 8 + tg * 2;
        av[nt][0] = __ldg(as_ + gc);     av[nt][1] = __ldg(as_ + gc + 1);
        dv[nt][0] = __ldg(ad_ + gc);     dv[nt][1] = __ldg(ad_ + gc + 1);
    }
    const bool two = (C == 16);
    const int hd0 = (bn + wn) / C;
    #pragma unroll
    for (int mt = 0; mt < 4; mt++) {
        #pragma unroll
        for (int hh = 0; hh < 2; hh++) {
            int row = bm + wm + mt * 16 + gid + hh * 8;
            float pes[2] = {0.f, 0.f}, ped[2] = {0.f, 0.f};
            #pragma unroll
            for (int nt = 0; nt < 4; nt++) {
                int sp = two ? (nt >> 1) : 0;
                float a0 = acc[mt][nt][hh * 2 + 0];
                float a1 = acc[mt][nt][hh * 2 + 1];
                pes[sp] += a0 * av[nt][0] + a1 * av[nt][1];
                ped[sp] += a0 * dv[nt][0] + a1 * dv[nt][1];
            }
            #pragma unroll
            for (int off = 1; off <= 2; off <<= 1) {
                pes[0] += __shfl_xor_sync(0xffffffffu, pes[0], off);
                ped[0] += __shfl_xor_sync(0xffffffffu, ped[0], off);
                pes[1] += __shfl_xor_sync(0xffffffffu, pes[1], off);
                ped[1] += __shfl_xor_sync(0xffffffffu, ped[1], off);
            }
            if (tg == 0 && row < M) {
                atomicAdd(&g_es[row * 8 + hd0], pes[0]);
                atomicAdd(&g_ed[row * 8 + hd0], ped[0]);
                if (two) {
                    atomicAdd(&g_es[row * 8 + hd0 + 1], pes[1]);
                    atomicAdd(&g_ed[row * 8 + hd0 + 1], ped[1]);
                }
            }
        }
    }
}

// ---------------- edge softmax (warp per dst node) ---------------------------
__global__ void k_softmax() {
    int w = (blockIdx.x * blockDim.x + threadIdx.x) >> 5;
    if (w >= NN) return;
    int lane = threadIdx.x & 31;
    int head = lane & 7, sub = lane >> 3;
    int beg = g_off[w];
    int deg = g_off[w + 1] - beg;
    float edv = g_ed[w * 8 + head];
    float mx = -3.0e38f;
    for (int i = sub; i < deg; i += 4) {
        int s = g_src[beg + i];
        float e = g_es[s * 8 + head] + edv;
        e = e > 0.f ? e : 0.2f * e;
        g_alpha[(beg + i) * 8 + head] = e;
        mx = fmaxf(mx, e);
    }
    mx = fmaxf(mx, __shfl_xor_sync(0xffffffffu, mx, 8));
    mx = fmaxf(mx, __shfl_xor_sync(0xffffffffu, mx, 16));
    float sm = 0.f;
    for (int i = sub; i < deg; i += 4) {
        float ex = __expf(g_alpha[(beg + i) * 8 + head] - mx);
        g_alpha[(beg + i) * 8 + head] = ex;
        sm += ex;
    }
    sm += __shfl_xor_sync(0xffffffffu, sm, 8);
    sm += __shfl_xor_sync(0xffffffffu, sm, 16);
    if (lane < 8) g_inv[w * 8 + lane] = 1.f / sm;
}

// ---------------- aggregation (fp16 gather, 2-edge unrolled) -----------------
template <int WR, int LOG2C, bool ELU, int LOG2S, bool RND>
__global__ void k_agg(const float* __restrict__ bias) {
    int gw = (blockIdx.x * blockDim.x + threadIdx.x) >> 5;
    int node = gw >> LOG2S;
    if (node >= NN) return;
    int part = gw & ((1 << LOG2S) - 1);
    const int lane = threadIdx.x & 31;
    const int Fout = (WR * 128) << LOG2S;
    const int base = part * (WR * 128);
    int beg = g_off[node], end = g_off[node + 1];

    float4 acc[WR];
    #pragma unroll
    for (int r = 0; r < WR; r++) acc[r] = make_float4(0.f, 0.f, 0.f, 0.f);

    int i = beg;
    for (; i + 2 <= end; i += 2) {
        int s0 = g_src[i], s1 = g_src[i + 1];
        float a0 = (lane < 8) ? g_alpha[i * 8 + lane] : 0.f;
        float a1 = (lane < 8) ? g_alpha[i * 8 + 8 + lane] : 0.f;
        const uint2* h0 = (const uint2*)(g_h16 + (size_t)s0 * Fout + base);
        const uint2* h1 = (const uint2*)(g_h16 + (size_t)s1 * Fout + base);
        #pragma unroll
        for (int r = 0; r < WR; r++) {
            int f = base + r * 128 + lane * 4;
            int hh = f >> LOG2C;
            uint2 u0 = __ldg(h0 + r * 32 + lane);
            uint2 u1 = __ldg(h1 + r * 32 + lane);
            float al0 = __shfl_sync(0xffffffffu, a0, hh);
            float al1 = __shfl_sync(0xffffffffu, a1, hh);
            float2 lo0 = __half22float2(*(__half2*)&u0.x);
            float2 hi0 = __half22float2(*(__half2*)&u0.y);
            float2 lo1 = __half22float2(*(__half2*)&u1.x);
            float2 hi1 = __half22float2(*(__half2*)&u1.y);
            acc[r].x = fmaf(al0, lo0.x, fmaf(al1, lo1.x, acc[r].x));
            acc[r].y = fmaf(al0, lo0.y, fmaf(al1, lo1.y, acc[r].y));
            acc[r].z = fmaf(al0, hi0.x, fmaf(al1, hi1.x, acc[r].z));
            acc[r].w = fmaf(al0, hi0.y, fmaf(al1, hi1.y, acc[r].w));
        }
    }
    if (i < end) {
        int s0 = g_src[i];
        float a0 = (lane < 8) ? g_alpha[i * 8 + lane] : 0.f;
        const uint2* h0 = (const uint2*)(g_h16 + (size_t)s0 * Fout + base);
        #pragma unroll
        for (int r = 0; r < WR; r++) {
            int f = base + r * 128 + lane * 4;
            float al0 = __shfl_sync(0xffffffffu, a0, f >> LOG2C);
            uint2 u0 = __ldg(h0 + r * 32 + lane);
            float2 lo0 = __half22float2(*(__half2*)&u0.x);
            float2 hi0 = __half22float2(*(__half2*)&u0.y);
            acc[r].x = fmaf(al0, lo0.x, acc[r].x);
            acc[r].y = fmaf(al0, lo0.y, acc[r].y);
            acc[r].z = fmaf(al0, hi0.x, acc[r].z);
            acc[r].w = fmaf(al0, hi0.y, acc[r].w);
        }
    }

    float* op = g_bufB + (size_t)node * Fout;
    #pragma unroll
    for (int r = 0; r < WR; r++) {
        int f = base + r * 128 + lane * 4;
        float inv = g_inv[node * 8 + (f >> LOG2C)];
        float4 b4 = __ldg((const float4*)(bias + f));
        float4 v;
        v.x = fmaf(acc[r].x, inv, b4.x);
        v.y = fmaf(acc[r].y, inv, b4.y);
        v.z = fmaf(acc[r].z, inv, b4.z);
        v.w = fmaf(acc[r].w, inv, b4.w);
        if (ELU) {
            v.x = v.x > 0.f ? v.x : expm1f(v.x);
            v.y = v.y > 0.f ? v.y : expm1f(v.y);
            v.z = v.z > 0.f ? v.z : expm1f(v.z);
            v.w = v.w > 0.f ? v.w : expm1f(v.w);
        }
        if (RND) {
            v.x = tf32r(v.x); v.y = tf32r(v.y);
            v.z = tf32r(v.z); v.w = tf32r(v.w);
        }
        *(float4*)(op + f) = v;
    }
}

// ---------------- pooling (init also clears CSR scratch) ---------------------
__global__ void k_pool_init() {
    int i = blockIdx.x * blockDim.x + threadIdx.x;
    if (i < GMAX * 512) g_pool[i] = 0.f;
    if (i < GMAX) g_cnt[i] = 0.f;
    if (i < NN) { g_deg[i] = 0; g_fill[i] = 0; }
}

__global__ void k_pool(const int* __restrict__ batch) {
    int f = threadIdx.x;
    int n0 = blockIdx.x * 512;
    int n1 = n0 + 512; if (n1 > NN) n1 = NN;
    if (n0 >= NN) return;
    float acc = 0.f;
    int cur = __ldg(&batch[n0]);
    float cnt = 0.f;
    for (int n = n0; n < n1; n++) {
        int b = __ldg(&batch[n]);
        if (b != cur) {
            atomicAdd(&g_pool[cur * 512 + f], acc);
            if (f == 0) atomicAdd(&g_cnt[cur], cnt);
            acc = 0.f; cnt = 0.f; cur = b;
        }
        acc += g_bufB[(size_t)n * 512 + f];
        cnt += 1.f;
    }
    atomicAdd(&g_pool[cur * 512 + f], acc);
    if (f == 0) atomicAdd(&g_cnt[cur], cnt);
}

// ---------------- MLP head ---------------------------------------------------
__global__ void k_mlp1(const float* __restrict__ lw1, const float* __restrict__ lb1) {
    int t = blockIdx.x * blockDim.x + threadIdx.x;
    if (t >= GMAX * 32) return;
    int g = t >> 5, j = t & 31;
    float inv = 1.f / fmaxf(g_cnt[g], 1.f);
    const float* pp = g_pool + g * 512;
    const float* wp = lw1 + j * 512;
    float s = 0.f;
    for (int k = 0; k < 512; k++) s += pp[k] * __ldg(wp + k);
    s = s * inv + __ldg(lb1 + j);
    g_mlp[t] = s > 0.f ? s : expm1f(s);
}

__global__ void k_mlp2(const float* __restrict__ lw2, const float* __restrict__ lb2,
                       float* __restrict__ out) {
    int t = threadIdx.x;
    if (t >= GMAX * 2) return;
    int g = t >> 1, o = t & 1;
    const float* mp = g_mlp + g * 32;
    const float* wp = lw2 + o * 32;
    float s = 0.f;
    #pragma unroll
    for (int k = 0; k < 32; k++) s += mp[k] * __ldg(wp + k);
    out[t] = s + __ldg(lb2 + o);
}

// ---------------- launch -----------------------------------------------------
extern "C" void kernel_launch(void* const* d_in, const int* in_sizes, int n_in,
                              void* d_out, int out_size) {
    const float* x     = (const float*)d_in[0];
    const int*   ei    = (const int*)  d_in[1];
    const int*   batch = (const int*)  d_in[2];
    const float *W[4], *as_[4], *ad_[4], *bb[4];
    for (int l = 0; l < 4; l++) {
        W[l]   = (const float*)d_in[3 + l * 4];
        as_[l] = (const float*)d_in[4 + l * 4];
        ad_[l] = (const float*)d_in[5 + l * 4];
        bb[l]  = (const float*)d_in[6 + l * 4];
    }
    const float* lw1 = (const float*)d_in[19];
    const float* lb1 = (const float*)d_in[20];
    const float* lw2 = (const float*)d_in[21];
    const float* lb2 = (const float*)d_in[22];
    float* out = (float*)d_out;

    const int woff[4] = {0, 65536, 196608, 229376};
    float* wr_base;
    cudaGetSymbolAddress((void**)&wr_base, g_wr);
    float* xr_base;
    cudaGetSymbolAddress((void**)&xr_base, g_xr);

    const int Fo[4]  = {512, 256, 128, 512};
    const int Cc[4]  = {64, 32, 16, 64};
    const int Fin[4] = {128, 512, 256, 128};

    // 0: fused rounding
    k_round_all<<<(X4 + W4T + 255) / 256, 256>>>(x, W[0], W[1], W[2], W[3]);
    // 1: zero es/ed for layer 0
    k_zero_att<<<(NN * 8 + 255) / 256, 256>>>();
    // 2: CSR count (independent of GEMM)
    k_count<<<(ETOT + 255) / 256, 256>>>(ei);
    // 3: GEMM layer 0 (profiled index)
    {
        dim3 gg(Fo[0] / 128, (NN + 127) / 128);
        k_gemm_tc<<<gg, 256>>>(xr_base, wr_base + woff[0], as_[0], ad_[0],
                               NN, Fo[0], Fin[0], Cc[0]);
    }
    // 4-5: finish CSR
    k_scan<<<1, 1024>>>();
    k_fill<<<(ETOT + 255) / 256, 256>>>(ei);
    // layer 0 softmax + agg
    k_softmax<<<(NN + 7) / 8, 256>>>();
    {
        int nb = (NN * 2 * 32 + 255) / 256;
        k_agg<2, 6, true, 1, true><<<nb, 256>>>(bb[0]);
    }

    for (int l = 1; l < 4; l++) {
        k_zero_att<<<(NN * 8 + 255) / 256, 256>>>();
        dim3 gg(Fo[l] / 128, (NN + 127) / 128);
        k_gemm_tc<<<gg, 256>>>(nullptr, wr_base + woff[l], as_[l], ad_[l],
                               NN, Fo[l], Fin[l], Cc[l]);
        k_softmax<<<(NN + 7) / 8, 256>>>();
        if (l == 1) {
            int nb = (NN * 2 * 32 + 255) / 256;
            k_agg<1, 5, true, 1, true><<<nb, 256>>>(bb[l]);
        } else if (l == 2) {
            int nb = (NN * 32 + 255) / 256;
            k_agg<1, 4, true, 0, true><<<nb, 256>>>(bb[l]);
        } else {
            int nb = (NN * 2 * 32 + 255) / 256;
            k_agg<2, 6, false, 1, false><<<nb, 256>>>(bb[l]);
        }
    }

    k_pool_init<<<(NN + 255) / 256, 256>>>();
    k_pool<<<(NN + 511) / 512, 512>>>(batch);
    k_mlp1<<<8, 256>>>(lw1, lb1);
    k_mlp2<<<1, 128>>>(lw2, lb2, out);
}